// round 14
// baseline (speedup 1.0000x reference)
#include <cuda_runtime.h>
#include <cuda_bf16.h>
#include <math.h>
#include <stdint.h>

#define BATCH 8
#define NPTS  16384
#define M_KV  64
#define TOTM  (BATCH*NPTS)
#define P     16
#define PP    20
typedef unsigned long long ull;

// ======== PTX helpers ========
__device__ __forceinline__ uint32_t smem_u32(const void* p) {
    uint32_t a;
    asm("{ .reg .u64 t; cvta.to.shared.u64 t, %1; cvt.u32.u64 %0, t; }" : "=r"(a) : "l"(p));
    return a;
}
#define CP16(dst, src) asm volatile("cp.async.cg.shared.global [%0], [%1], 16;" :: "r"(dst), "l"(src) : "memory")
#define CP_COMMIT()    asm volatile("cp.async.commit_group;" ::: "memory")
#define CP_WAIT0()     asm volatile("cp.async.wait_group 0;" ::: "memory")
__device__ __forceinline__ void ldsm4(uint32_t* r, uint32_t addr) {
    asm volatile("ldmatrix.sync.aligned.m8n8.x4.shared.b16 {%0,%1,%2,%3}, [%4];"
        : "=r"(r[0]), "=r"(r[1]), "=r"(r[2]), "=r"(r[3]) : "r"(addr));
}
__device__ __forceinline__ void mma16816(float* c, const uint32_t* a, uint32_t b0, uint32_t b1) {
    asm volatile("mma.sync.aligned.m16n8k16.row.col.f32.bf16.bf16.f32 "
        "{%0,%1,%2,%3}, {%4,%5,%6,%7}, {%8,%9}, {%0,%1,%2,%3};"
        : "+f"(c[0]), "+f"(c[1]), "+f"(c[2]), "+f"(c[3])
        : "r"(a[0]), "r"(a[1]), "r"(a[2]), "r"(a[3]), "r"(b0), "r"(b1));
}
#define SW64(o) ((o) ^ (((o) >> 3) & 0x30))
__device__ __forceinline__ void fma2(ull& a, ull x, ull w) {
    asm("fma.rn.f32x2 %0, %1, %2, %0;" : "+l"(a) : "l"(x), "l"(w));
}
__device__ __forceinline__ float fold2(ull v) { float lo,hi; asm("mov.b64 {%0,%1}, %2;" : "=f"(lo),"=f"(hi) : "l"(v)); return lo+hi; }
__device__ __forceinline__ void unpack2(ull v, float& lo, float& hi) { asm("mov.b64 {%0,%1}, %2;" : "=f"(lo),"=f"(hi) : "l"(v)); }
__device__ __forceinline__ ull pack2(float lo, float hi) { ull r; asm("mov.b64 %0, {%1,%2};" : "=l"(r) : "f"(lo),"f"(hi)); return r; }
__device__ __forceinline__ uint32_t packbf(float v0, float v1, float& r0, float& r1) {
    __nv_bfloat16 h0 = __float2bfloat16_rn(v0);
    __nv_bfloat16 h1 = __float2bfloat16_rn(v1);
    r0 = v0 - __bfloat162float(h0);
    r1 = v1 - __bfloat162float(h1);
    unsigned short a = *(unsigned short*)&h0, b = *(unsigned short*)&h1;
    return (uint32_t)a | ((uint32_t)b << 16);
}
__device__ __forceinline__ uint32_t packlo(float l0, float l1) {
    __nv_bfloat16 a = __float2bfloat16_rn(l0);
    __nv_bfloat16 b = __float2bfloat16_rn(l1);
    unsigned short x = *(unsigned short*)&a, y = *(unsigned short*)&b;
    return (uint32_t)x | ((uint32_t)y << 16);
}

// ======== global scratch ========
#define SZ ((size_t)TOTM * 256)
__device__ __nv_bfloat16 g_X0h[SZ], g_X0l[SZ], g_X1h[SZ], g_X1l[SZ], g_Z2h[SZ], g_Z2l[SZ];
__device__ float g_Q[SZ];
__device__ __nv_bfloat16 g_Bh[12*65536], g_Bl[12*65536];
__device__ float g_WkT[65536], g_WvT[65536];
__device__ float g_Kt[BATCH*8*32*M_KV];
__device__ float g_Vt[BATCH*32*256*2];
__device__ __forceinline__ __nv_bfloat16* selH(int s){ return s==0?g_X0h:(s==1?g_X1h:g_Z2h); }
__device__ __forceinline__ __nv_bfloat16* selL(int s){ return s==0?g_X0l:(s==1?g_X1l:g_Z2l); }

// ======== prep kernels ========
__global__ void conv_w(const float* __restrict__ qp_W2, const float* __restrict__ in_W,
                       const float* __restrict__ out_W, const float* __restrict__ net2_W,
                       const float* __restrict__ net1_W) {
    int n = blockIdx.x, mat = blockIdx.y, k = threadIdx.x;
    if (mat >= 12) {
        const float* src = in_W + (size_t)(mat == 12 ? 256 : 512) * 256;
        float* dst = (mat == 12) ? g_WkT : g_WvT;
        dst[k*256 + n] = src[n*256 + k];
        return;
    }
    const float* src;
    switch (mat) {
        case 0: src = qp_W2; break;
        case 1: src = in_W;  break;
        case 2: src = out_W; break;
        default: src = (mat < 8) ? net2_W + (mat-3)*65536 : net1_W + (mat-8)*65536;
    }
    float w = src[n*256 + k];
    __nv_bfloat16 h = __float2bfloat16_rn(w);
    g_Bh[mat*65536 + n*256 + k] = h;
    g_Bl[mat*65536 + n*256 + k] = __float2bfloat16_rn(w - __bfloat162float(h));
}

__global__ void kv_kernel(const float* __restrict__ z_multi,
                          const float* __restrict__ lnkv_g, const float* __restrict__ lnkv_b,
                          const float* __restrict__ in_b) {
    __shared__ float kvn[8][256];
    int t = threadIdx.x, lane = t & 31, w = t >> 5;
    int row0 = blockIdx.x * 8;
    {
        int row = row0 + w;
        float v[8];
        float s = 0.f, ss = 0.f;
        #pragma unroll
        for (int j = 0; j < 8; ++j) {
            v[j] = z_multi[(size_t)row*256 + lane*8 + j];
            s += v[j]; ss += v[j]*v[j];
        }
        #pragma unroll
        for (int o = 16; o; o >>= 1) {
            s  += __shfl_xor_sync(0xffffffffu, s,  o);
            ss += __shfl_xor_sync(0xffffffffu, ss, o);
        }
        float mu = s * (1.f/256.f);
        float rstd = rsqrtf(ss * (1.f/256.f) - mu*mu + 1e-5f);
        #pragma unroll
        for (int j = 0; j < 8; ++j) {
            int d = lane*8 + j;
            kvn[w][d] = (v[j] - mu) * rstd * lnkv_g[d] + lnkv_b[d];
        }
    }
    __syncthreads();
    float aK[8], aV[8];
    float bK = in_b[256+t], bV = in_b[512+t];
    #pragma unroll
    for (int i = 0; i < 8; ++i) { aK[i] = bK; aV[i] = bV; }
    #pragma unroll 4
    for (int d = 0; d < 256; ++d) {
        float wk = g_WkT[d*256 + t];
        float wv = g_WvT[d*256 + t];
        #pragma unroll
        for (int i = 0; i < 8; ++i) {
            float x = kvn[i][d];
            aK[i] += x * wk;
            aV[i] += x * wv;
        }
    }
    #pragma unroll
    for (int i = 0; i < 8; ++i) {
        int row = row0 + i, b = row >> 6, m = row & 63;
        g_Kt[((b*8 + (t>>5))*32 + (t&31))*M_KV + m] = aK[i];
        g_Vt[((b*32 + (m>>1))*256 + t)*2 + (m&1)] = aV[i];
    }
}

// ======== warp-MMA GEMM (templated mode), stage-paired double buffer ========
#define OFF_AL 8192u
#define OFF_BH 16384u
#define OFF_BL 32768u
#define SLAB_BYTES 49152u
#define STAGE_BYTES 98304u
#define GEMM_SMEM (2*98304)
#define MODE_LN 0
#define MODE_Q 1
#define MODE_BIAS 2

template<bool COMPUTE_A>
__device__ __forceinline__ void load_chunk(uint32_t base,
        const __nv_bfloat16* AH, const __nv_bfloat16* AL,
        const __nv_bfloat16* BH, const __nv_bfloat16* BL,
        int m0, int c, int tid,
        float cxp, float cyp,
        const float* __restrict__ qpW1, const float* __restrict__ qpb1) {
    int r = tid >> 2, seg = tid & 3;
    uint32_t sA = base + SW64((uint32_t)(r*64 + seg*16));
    if (COMPUTE_A) {
        int h0 = c*32 + seg*8;
        #pragma unroll
        for (int j2 = 0; j2 < 4; ++j2) {
            int h = h0 + j2*2;
            float4 wv = *(const float4*)(qpW1 + 2*h);
            float2 bv = *(const float2*)(qpb1 + h);
            float u0 = wv.x*cxp + wv.y*cyp + bv.x;
            float u1 = wv.z*cxp + wv.w*cyp + bv.y;
            float v0 = 0.5f*u0*(1.f + erff(u0*0.70710678118654752f));
            float v1 = 0.5f*u1*(1.f + erff(u1*0.70710678118654752f));
            float l0, l1;
            uint32_t hp = packbf(v0, v1, l0, l1);
            uint32_t lp = packlo(l0, l1);
            asm volatile("st.shared.b32 [%0], %1;" :: "r"(sA + j2*4), "r"(hp) : "memory");
            asm volatile("st.shared.b32 [%0], %1;" :: "r"(sA + OFF_AL + j2*4), "r"(lp) : "memory");
        }
    } else {
        size_t aofs = (size_t)(m0 + r)*256 + c*32 + seg*8;
        CP16(sA, AH + aofs);
        CP16(sA + OFF_AL, AL + aofs);
    }
    #pragma unroll
    for (int it = 0; it < 2; ++it) {
        int row = r + it*128;
        size_t bofs = (size_t)row*256 + c*32 + seg*8;
        uint32_t sB = base + OFF_BH + SW64((uint32_t)(row*64 + seg*16));
        CP16(sB, BH + bofs);
        CP16(sB + 16384u, BL + bofs);
    }
}

template<int MODE>
__global__ void __launch_bounds__(512, 1)
gemm_mma(int nsrc, int srcA1, int matB1, int dst,
         const float* __restrict__ bias, float scale,
         const float* __restrict__ lng, const float* __restrict__ lnb,
         const float* __restrict__ coords,
         const float* __restrict__ qpW1, const float* __restrict__ qpb1) {
    extern __shared__ char smraw[];
    uint32_t sb = smem_u32(smraw);
    int tid = threadIdx.x, lane = tid & 31, w = tid >> 5;
    int wn = w & 3, wm = w >> 2;
    int m_block = blockIdx.x * 128;

    const __nv_bfloat16* AH = selH(srcA1);
    const __nv_bfloat16* AL = selL(srcA1);
    const __nv_bfloat16* BH = g_Bh + (size_t)matB1*65536;
    const __nv_bfloat16* BL = g_Bl + (size_t)matB1*65536;

    float cxp = 0.f, cyp = 0.f;
    if (MODE == MODE_LN) {
        float2 xy = *(const float2*)(coords + 2*(m_block + (tid >> 2)));
        cxp = xy.x; cyp = xy.y;
    }
    constexpr bool CA = (MODE == MODE_LN);

    int sub = lane & 7, blk = lane >> 3;
    int rowoff = sub + ((blk & 1) << 3);
    uint32_t koffB = (uint32_t)((blk >> 1) << 4);
    uint32_t aoff[2][2], boff[4][2];
    #pragma unroll
    for (int mt = 0; mt < 2; ++mt)
        #pragma unroll
        for (int kh = 0; kh < 2; ++kh)
            aoff[mt][kh] = SW64((uint32_t)((wm*32 + mt*16 + rowoff)*64 + kh*32) + koffB);
    #pragma unroll
    for (int ng = 0; ng < 4; ++ng)
        #pragma unroll
        for (int kh = 0; kh < 2; ++kh)
            boff[ng][kh] = SW64((uint32_t)((wn*64 + ng*16 + rowoff)*64 + kh*32) + koffB);

    float c[2][8][4];
    #pragma unroll
    for (int mt = 0; mt < 2; ++mt)
        #pragma unroll
        for (int nt = 0; nt < 8; ++nt)
            #pragma unroll
            for (int i = 0; i < 4; ++i) c[mt][nt][i] = 0.f;

    int nst = nsrc * 4;
    load_chunk<CA>(sb, AH, AL, BH, BL, m_block, 0, tid, cxp, cyp, qpW1, qpb1);
    load_chunk<CA>(sb + SLAB_BYTES, AH, AL, BH, BL, m_block, 1, tid, cxp, cyp, qpW1, qpb1);
    CP_COMMIT();

    for (int st = 0; st < nst; ++st) {
        CP_WAIT0();
        __syncthreads();
        if (st + 1 < nst) {
            int g = 2*(st+1), cc = g & 7;
            uint32_t nb = sb + ((st+1) & 1)*STAGE_BYTES;
            load_chunk<CA>(nb, AH, AL, BH, BL, m_block, cc, tid, cxp, cyp, qpW1, qpb1);
            load_chunk<CA>(nb + SLAB_BYTES, AH, AL, BH, BL, m_block, cc+1, tid, cxp, cyp, qpW1, qpb1);
            CP_COMMIT();
        }
        uint32_t stbase = sb + (st & 1)*STAGE_BYTES;
        #pragma unroll
        for (int sl = 0; sl < 2; ++sl) {
            uint32_t base = stbase + sl*SLAB_BYTES;
            #pragma unroll
            for (int kh = 0; kh < 2; ++kh) {
                uint32_t ah[2][4], al[2][4];
                ldsm4(ah[0], base + aoff[0][kh]);
                ldsm4(ah[1], base + aoff[1][kh]);
                ldsm4(al[0], base + OFF_AL + aoff[0][kh]);
                ldsm4(al[1], base + OFF_AL + aoff[1][kh]);
                #pragma unroll
                for (int ng = 0; ng < 4; ++ng) {
                    uint32_t bh[4], bl[4];
                    ldsm4(bh, base + OFF_BH + boff[ng][kh]);
                    ldsm4(bl, base + OFF_BL + boff[ng][kh]);
                    #pragma unroll
                    for (int mt = 0; mt < 2; ++mt) {
                        mma16816(c[mt][2*ng],   ah[mt], bh[0], bh[2]);
                        mma16816(c[mt][2*ng+1], ah[mt], bh[1], bh[3]);
                        mma16816(c[mt][2*ng],   al[mt], bh[0], bh[2]);
                        mma16816(c[mt][2*ng+1], al[mt], bh[1], bh[3]);
                        mma16816(c[mt][2*ng],   ah[mt], bl[0], bl[2]);
                        mma16816(c[mt][2*ng+1], ah[mt], bl[1], bl[3]);
                    }
                }
            }
        }
    }
    __syncthreads();

    // ======== fragment-direct epilogue ========
    float* sLN  = (float*)smraw;
    float* sLN2 = sLN + 512;
    int r4 = lane >> 2, kp2 = (lane & 3)*2;

    if (bias) {
        #pragma unroll
        for (int nt = 0; nt < 8; ++nt) {
            float2 bv = *(const float2*)(bias + wn*64 + nt*8 + kp2);
            #pragma unroll
            for (int mt = 0; mt < 2; ++mt) {
                c[mt][nt][0] += bv.x; c[mt][nt][1] += bv.y;
                c[mt][nt][2] += bv.x; c[mt][nt][3] += bv.y;
            }
        }
    }

    float muv[2][2], rsv[2][2];
    if (MODE == MODE_LN) {
        #pragma unroll
        for (int mt = 0; mt < 2; ++mt)
            #pragma unroll
            for (int hf = 0; hf < 2; ++hf) {
                float s = 0.f, ss = 0.f;
                #pragma unroll
                for (int nt = 0; nt < 8; ++nt) {
                    float v0 = c[mt][nt][2*hf], v1 = c[mt][nt][2*hf+1];
                    s += v0 + v1; ss += v0*v0 + v1*v1;
                }
                s  += __shfl_xor_sync(0xffffffffu, s, 1);  s += __shfl_xor_sync(0xffffffffu, s, 2);
                ss += __shfl_xor_sync(0xffffffffu, ss, 1); ss += __shfl_xor_sync(0xffffffffu, ss, 2);
                if ((lane & 3) == 0) {
                    int rl = wm*32 + mt*16 + hf*8 + r4;
                    sLN[rl*4 + wn] = s; sLN2[rl*4 + wn] = ss;
                }
            }
        __syncthreads();
        #pragma unroll
        for (int mt = 0; mt < 2; ++mt)
            #pragma unroll
            for (int hf = 0; hf < 2; ++hf) {
                int rl = wm*32 + mt*16 + hf*8 + r4;
                float S  = sLN[rl*4] + sLN[rl*4+1] + sLN[rl*4+2] + sLN[rl*4+3];
                float SS = sLN2[rl*4] + sLN2[rl*4+1] + sLN2[rl*4+2] + sLN2[rl*4+3];
                float mu = S * (1.f/256.f);
                muv[mt][hf] = mu;
                rsv[mt][hf] = rsqrtf(SS * (1.f/256.f) - mu*mu + 1e-5f);
            }
    }

    __nv_bfloat16* oH = selH(dst);
    __nv_bfloat16* oL = selL(dst);
    #pragma unroll
    for (int nt = 0; nt < 8; ++nt) {
        int col = wn*64 + nt*8 + kp2;
        float lg0 = 0.f, lg1 = 0.f, lb0 = 0.f, lb1 = 0.f;
        if (MODE == MODE_LN) {
            float2 lg = *(const float2*)(lng + col);
            float2 lb = *(const float2*)(lnb + col);
            lg0 = lg.x; lg1 = lg.y; lb0 = lb.x; lb1 = lb.y;
        }
        #pragma unroll
        for (int mt = 0; mt < 2; ++mt)
            #pragma unroll
            for (int hf = 0; hf < 2; ++hf) {
                int pt = m_block + wm*32 + mt*16 + hf*8 + r4;
                float v0 = c[mt][nt][2*hf], v1 = c[mt][nt][2*hf+1];
                if (MODE == MODE_LN) {
                    v0 = (v0 - muv[mt][hf]) * rsv[mt][hf] * lg0 + lb0;
                    v1 = (v1 - muv[mt][hf]) * rsv[mt][hf] * lg1 + lb1;
                }
                if (MODE == MODE_Q) {
                    *(float2*)(g_Q + (size_t)pt*256 + col) = make_float2(v0*scale, v1*scale);
                } else {
                    float l0, l1;
                    uint32_t hp = packbf(v0, v1, l0, l1);
                    uint32_t lp = packlo(l0, l1);
                    *(uint32_t*)(oH + (size_t)pt*256 + col) = hp;
                    *(uint32_t*)(oL + (size_t)pt*256 + col) = lp;
                }
            }
    }
}

// ======== fused MFN kernel: L0..L4 + fin + irfft ========
#define FX_BYTES 131072u
#define FSLAB 49152u
#define FUSED_SMEM (131072 + 2*49152)
#define XPITCH 260
// fin-stage smem layout (aliases everything after mainloop):
//   sXf fp32 [128][XPITCH]  @ float offset 0      (133120 B)
//   sF  fp32 [128][36]      @ float offset 33280  (18432 B)
//   sTab fp32 [32]          @ float offset 37888

__global__ void __launch_bounds__(512, 1)
mfn_fused(const float* __restrict__ net1_b,
          const float* __restrict__ gW, const float* __restrict__ gb,
          const float* __restrict__ gmu, const float* __restrict__ gga,
          const float* __restrict__ coords,
          const float* __restrict__ fin_W, const float* __restrict__ fin_b,
          float* __restrict__ out) {
    extern __shared__ char smraw[];
    uint32_t sb = smem_u32(smraw);
    uint32_t stoff = sb + FX_BYTES;
    int tid = threadIdx.x, lane = tid & 31, w = tid >> 5;
    int wn = w & 3, wm = w >> 2;
    int m_block = blockIdx.x * 128;

    int sub = lane & 7, blk = lane >> 3;
    int rowoff = sub + ((blk & 1) << 3);
    uint32_t koffB = (uint32_t)((blk >> 1) << 4);
    uint32_t aoff[2][2], boff[4][2];
    #pragma unroll
    for (int mt = 0; mt < 2; ++mt)
        #pragma unroll
        for (int kh = 0; kh < 2; ++kh)
            aoff[mt][kh] = SW64((uint32_t)((wm*32 + mt*16 + rowoff)*64 + kh*32) + koffB);
    #pragma unroll
    for (int ng = 0; ng < 4; ++ng)
        #pragma unroll
        for (int kh = 0; kh < 2; ++kh)
            boff[ng][kh] = SW64((uint32_t)((wn*64 + ng*16 + rowoff)*64 + kh*32) + koffB);

    int r4 = lane >> 2, kp2 = (lane & 3)*2;
    float cx[2][2], cy[2][2], rr2[2][2];
    #pragma unroll
    for (int mt = 0; mt < 2; ++mt)
        #pragma unroll
        for (int hf = 0; hf < 2; ++hf) {
            int pt = m_block + wm*32 + mt*16 + hf*8 + r4;
            float2 xy = *(const float2*)(coords + 2*pt);
            cx[mt][hf] = xy.x; cy[mt][hf] = xy.y; rr2[mt][hf] = xy.x*xy.x + xy.y*xy.y;
        }

    auto prefetch = [&](int L, int i, uint32_t stb) {
        bool loadA; int ch, matB;
        if (L == 0)      { loadA = true;  ch = i;     matB = 3; }
        else if (i < 8)  { loadA = false; ch = i;     matB = 8 + (L-1); }
        else             { loadA = true;  ch = i - 8; matB = 3 + L; }
        const __nv_bfloat16* BHp = g_Bh + (size_t)matB*65536;
        const __nv_bfloat16* BLp = g_Bl + (size_t)matB*65536;
        int r = tid >> 2, seg = tid & 3;
        size_t go = (size_t)ch*32 + seg*8;
        if (loadA) {
            size_t aofs = (size_t)(m_block + r)*256 + go;
            uint32_t sA = stb + SW64((uint32_t)(r*64 + seg*16));
            CP16(sA, g_Z2h + aofs);
            CP16(sA + OFF_AL, g_Z2l + aofs);
        }
        #pragma unroll
        for (int it = 0; it < 2; ++it) {
            int row = r + it*128;
            uint32_t sB = stb + OFF_BH + SW64((uint32_t)(row*64 + seg*16));
            CP16(sB, BHp + (size_t)row*256 + go);
            CP16(sB + 16384u, BLp + (size_t)row*256 + go);
        }
    };

    float c[2][8][4];
    int s = 0;
    prefetch(0, 0, stoff);
    CP_COMMIT();

    for (int L = 0; L <= 4; ++L) {
        int np = (L == 0) ? 8 : 16;
        #pragma unroll
        for (int mt = 0; mt < 2; ++mt)
            #pragma unroll
            for (int nt = 0; nt < 8; ++nt)
                #pragma unroll
                for (int i = 0; i < 4; ++i) c[mt][nt][i] = 0.f;

        for (int i = 0; i < np; ++i) {
            CP_WAIT0();
            __syncthreads();
            {
                int nL = L, ni = i + 1;
                if (ni == np) { nL = L + 1; ni = 0; }
                if (nL <= 4) {
                    prefetch(nL, ni, stoff + (uint32_t)((s+1) & 1)*FSLAB);
                    CP_COMMIT();
                }
            }
            bool isx = (L > 0 && i < 8);
            uint32_t stb = stoff + (uint32_t)(s & 1)*FSLAB;
            uint32_t Abase = isx ? (sb + (uint32_t)i*16384u) : stb;
            uint32_t Bbase = stb;
            #pragma unroll
            for (int kh = 0; kh < 2; ++kh) {
                uint32_t ah[2][4], al[2][4];
                ldsm4(ah[0], Abase + aoff[0][kh]);
                ldsm4(ah[1], Abase + aoff[1][kh]);
                ldsm4(al[0], Abase + OFF_AL + aoff[0][kh]);
                ldsm4(al[1], Abase + OFF_AL + aoff[1][kh]);
                #pragma unroll
                for (int ng = 0; ng < 4; ++ng) {
                    uint32_t bh[4], bl[4];
                    ldsm4(bh, Bbase + OFF_BH + boff[ng][kh]);
                    ldsm4(bl, Bbase + OFF_BL + boff[ng][kh]);
                    #pragma unroll
                    for (int mt = 0; mt < 2; ++mt) {
                        mma16816(c[mt][2*ng],   ah[mt], bh[0], bh[2]);
                        mma16816(c[mt][2*ng+1], ah[mt], bh[1], bh[3]);
                        mma16816(c[mt][2*ng],   al[mt], bh[0], bh[2]);
                        mma16816(c[mt][2*ng+1], al[mt], bh[1], bh[3]);
                        mma16816(c[mt][2*ng],   ah[mt], bl[0], bl[2]);
                        mma16816(c[mt][2*ng+1], ah[mt], bl[1], bl[3]);
                    }
                }
            }
            ++s;
        }
        __syncthreads();   // all reads of x done before overwrite

        // ---- epilogue layer L ----
        float* sXf = (float*)smraw;
        #pragma unroll
        for (int nt = 0; nt < 8; ++nt) {
            int col = wn*64 + nt*8 + kp2;
            if (L > 0) {
                float2 bv = *(const float2*)(net1_b + (L-1)*256 + col);
                #pragma unroll
                for (int mt = 0; mt < 2; ++mt) {
                    c[mt][nt][0] += bv.x; c[mt][nt][1] += bv.y;
                    c[mt][nt][2] += bv.x; c[mt][nt][3] += bv.y;
                }
            }
            int idx = L*256 + col;
            float4 wv = *(const float4*)(gW + 2*idx);
            float4 mv = *(const float4*)(gmu + 2*idx);
            float2 bb = *(const float2*)(gb + idx);
            float2 gv = *(const float2*)(gga + idx);
            float mu20 = mv.x*mv.x + mv.y*mv.y;
            float mu21 = mv.z*mv.z + mv.w*mv.w;
            #pragma unroll
            for (int mt = 0; mt < 2; ++mt)
                #pragma unroll
                for (int hf = 0; hf < 2; ++hf) {
                    float x = cx[mt][hf], y = cy[mt][hf], r2 = rr2[mt][hf];
                    float D0 = r2 + mu20 - 2.f*(x*mv.x + y*mv.y);
                    float D1 = r2 + mu21 - 2.f*(x*mv.z + y*mv.w);
                    float v0 = c[mt][nt][2*hf] * (sinf(wv.x*x + wv.y*y + bb.x) * __expf(-0.5f*D0*gv.x));
                    float v1 = c[mt][nt][2*hf+1] * (sinf(wv.z*x + wv.w*y + bb.y) * __expf(-0.5f*D1*gv.y));
                    int rl = wm*32 + mt*16 + hf*8 + r4;
                    if (L < 4) {
                        float l0, l1;
                        uint32_t hp = packbf(v0, v1, l0, l1);
                        uint32_t lp = packlo(l0, l1);
                        uint32_t xo = sb + (uint32_t)(col >> 5)*16384u
                                    + SW64((uint32_t)(rl*64 + (col & 31)*2));
                        asm volatile("st.shared.b32 [%0], %1;" :: "r"(xo), "r"(hp) : "memory");
                        asm volatile("st.shared.b32 [%0], %1;" :: "r"(xo + OFF_AL), "r"(lp) : "memory");
                    } else {
                        sXf[rl*XPITCH + col]     = v0;
                        sXf[rl*XPITCH + col + 1] = v1;
                    }
                }
        }
    }
    __syncthreads();   // fp32 x fully in sXf

    // ======== fused fin + irfft ========
    {
        float* sXf = (float*)smraw;
        float* sF   = sXf + 128*XPITCH;        // [128][36]
        float* sTab = sF + 128*36;             // [32]
        if (tid < 16) {
            float sv, cv;
            sincosf(0.39269908169872414f * (float)tid, &sv, &cv);
            sTab[2*tid] = cv; sTab[2*tid+1] = sv;
        }
        int p = tid >> 2, j = tid & 3;
        // load this thread's x quarter into registers (h = j*64 .. j*64+63)
        ull xr[32];
        const float* xp = sXf + p*XPITCH + j*64;
        #pragma unroll
        for (int k2 = 0; k2 < 32; ++k2)
            xr[k2] = *(const ull*)(xp + 2*k2);
        const ull* Wb = (const ull*)(fin_W + j*64);
        #pragma unroll 4
        for (int g = 0; g < 36; ++g) {
            ull acc = 0ull;
            const ull* Wg = Wb + g*128;   // fin_W[g*256 + j*64] as ull index
            #pragma unroll
            for (int k2 = 0; k2 < 32; ++k2) fma2(acc, xr[k2], Wg[k2]);
            float sv = fold2(acc);
            sv += __shfl_xor_sync(0xffffffffu, sv, 1);
            sv += __shfl_xor_sync(0xffffffffu, sv, 2);
            if (j == 0) sF[p*36 + g] = sv + fin_b[g];
        }
        __syncthreads();
        // irfft: 128 points x 2 ch x 16 t = 4096 outputs, 8 per thread
        int pc = tid & 255;
        int pp2 = pc >> 1, ch = pc & 1;
        int tg = tid >> 8;                 // 0..1
        const float* Fp = &sF[pp2*36];
        int b = m_block >> 14;
        int n0p = (m_block & (NPTS-1)) + pp2;
        #pragma unroll
        for (int it = 0; it < 8; ++it) {
            int tt = tg + 2*it;
            float a = Fp[ch*2];
            float f8 = Fp[8*4 + ch*2];
            a += (tt & 1) ? -f8 : f8;
            #pragma unroll
            for (int fq = 1; fq < 8; ++fq) {
                float re = Fp[fq*4 + ch*2], im = Fp[fq*4 + ch*2 + 1];
                int k = (fq*tt) & 15;
                a += 2.f * (re*sTab[2*k] - im*sTab[2*k+1]);
            }
            out[(((b*16 + tt)*NPTS) + n0p)*2 + ch] = 0.25f * a;
        }
    }
}

// ======== attention (scalar) ========
#define ATTN_SMF (5120 + P*512)
__global__ void __launch_bounds__(256, 2) attn_kernel() {
    extern __shared__ float smf[];
    float* sA = smf;
    float* sS = sA + 5120;
    int t = threadIdx.x, lane = t & 31, w = t >> 5;
    int bid = blockIdx.x, b = bid >> 10, n0 = (bid & 1023) * P;
    size_t base = (size_t)(b*NPTS + n0) * 256;
    #pragma unroll
    for (int p = 0; p < P; ++p) sA[t*PP + p] = g_Q[base + (size_t)p*256 + t];
    __syncthreads();
    #pragma unroll
    for (int rep = 0; rep < 2; ++rep) {
        int pair = t + rep*256, hh = pair >> 6, m = pair & 63;
        const float* Kp = &g_Kt[((b*8 + hh)*32)*M_KV + m];
        ull a2[8];
        #pragma unroll
        for (int j = 0; j < 8; ++j) a2[j] = 0ull;
        #pragma unroll 4
        for (int k = 0; k < 32; ++k) {
            float kv = Kp[k*M_KV];
            ull kk = pack2(kv, kv);
            const ulonglong2* col = (const ulonglong2*)(sA + (hh*32 + k)*PP);
            #pragma unroll
            for (int q = 0; q < 4; ++q) { ulonglong2 x = col[q]; fma2(a2[2*q], x.x, kk); fma2(a2[2*q+1], x.y, kk); }
        }
        #pragma unroll
        for (int j = 0; j < 8; ++j) {
            float lo, hi; unpack2(a2[j], lo, hi);
            sS[(2*j)*512 + pair] = lo; sS[(2*j+1)*512 + pair] = hi;
        }
    }
    __syncthreads();
    for (int rr = 0; rr < 16; ++rr) {
        int r = w + rr*8, p = r >> 3, hh = r & 7;
        float* bs = &sS[p*512 + hh*64];
        float v0 = bs[lane], v1 = bs[lane+32];
        float mx = fmaxf(v0, v1);
        #pragma unroll
        for (int o = 16; o; o >>= 1) mx = fmaxf(mx, __shfl_xor_sync(0xffffffffu, mx, o));
        float e0 = __expf(v0-mx), e1 = __expf(v1-mx), sum = e0 + e1;
        #pragma unroll
        for (int o = 16; o; o >>= 1) sum += __shfl_xor_sync(0xffffffffu, sum, o);
        float inv = 1.f/sum;
        bs[lane] = e0*inv; bs[lane+32] = e1*inv;
    }
    __syncthreads();
    {
        int hh = t >> 5;
        ull acc[P];
        #pragma unroll
        for (int p = 0; p < P; ++p) acc[p] = 0ull;
        const float* Vb = g_Vt + b*32*512;
        #pragma unroll 2
        for (int m = 0; m < M_KV; m += 2) {
            ull vv = *(const ull*)(Vb + ((m>>1)*256 + t)*2);
            #pragma unroll
            for (int p = 0; p < P; ++p) fma2(acc[p], *(const ull*)(&sS[p*512 + hh*64 + m]), vv);
        }
        #pragma unroll
        for (int p = 0; p < P; ++p) {
            float v = fold2(acc[p]);
            __nv_bfloat16 h = __float2bfloat16_rn(v);
            g_X0h[base + (size_t)p*256 + t] = h;
            g_X0l[base + (size_t)p*256 + t] = __float2bfloat16_rn(v - __bfloat162float(h));
        }
    }
}

// ======== launch ========
extern "C" void kernel_launch(void* const* d_in, const int* in_sizes, int n_in,
                              void* d_out, int out_size) {
    const float* z_multi=(const float*)d_in[0];  const float* coords=(const float*)d_in[1];
    const float* gabor_W=(const float*)d_in[2];  const float* gabor_b=(const float*)d_in[3];
    const float* gabor_mu=(const float*)d_in[4]; const float* gabor_ga=(const float*)d_in[5];
    const float* net1_W=(const float*)d_in[6];   const float* net1_b=(const float*)d_in[7];
    const float* net2_W=(const float*)d_in[8];   const float* qp_W1=(const float*)d_in[9];
    const float* qp_b1=(const float*)d_in[10];   const float* qp_W2=(const float*)d_in[11];
    const float* qp_b2=(const float*)d_in[12];   const float* in_W=(const float*)d_in[13];
    const float* in_b=(const float*)d_in[14];    const float* out_W=(const float*)d_in[15];
    const float* out_b=(const float*)d_in[16];   const float* lnq_g=(const float*)d_in[17];
    const float* lnq_b=(const float*)d_in[18];   const float* lnkv_g=(const float*)d_in[19];
    const float* lnkv_b=(const float*)d_in[20];  const float* fin_W=(const float*)d_in[21];
    const float* fin_b=(const float*)d_in[22];
    float* out = (float*)d_out;

    cudaFuncSetAttribute(gemm_mma<MODE_LN>,   cudaFuncAttributeMaxDynamicSharedMemorySize, GEMM_SMEM);
    cudaFuncSetAttribute(gemm_mma<MODE_Q>,    cudaFuncAttributeMaxDynamicSharedMemorySize, GEMM_SMEM);
    cudaFuncSetAttribute(gemm_mma<MODE_BIAS>, cudaFuncAttributeMaxDynamicSharedMemorySize, GEMM_SMEM);
    cudaFuncSetAttribute(mfn_fused,           cudaFuncAttributeMaxDynamicSharedMemorySize, FUSED_SMEM);
    cudaFuncSetAttribute(attn_kernel, cudaFuncAttributeMaxDynamicSharedMemorySize, ATTN_SMF*4);

    conv_w<<<dim3(256,14), 256>>>(qp_W2, in_W, out_W, net2_W, net1_W);
    kv_kernel<<<BATCH*M_KV/8, 256>>>(z_multi, lnkv_g, lnkv_b, in_b);

    int G = TOTM/128;
    const float qscale = 0.17677669529663687f;  // 1/sqrt(32)
    gemm_mma<MODE_LN><<<G,512,GEMM_SMEM>>>(1, 0, 0, 1, qp_b2, 1.f, lnq_g, lnq_b, coords, qp_W1, qp_b1);
    gemm_mma<MODE_Q><<<G,512,GEMM_SMEM>>>(1, 1, 1, 0, in_b, qscale, 0, 0, coords, 0, 0);
    attn_kernel<<<BATCH*(NPTS/P), 256, ATTN_SMF*4>>>();
    gemm_mma<MODE_BIAS><<<G,512,GEMM_SMEM>>>(1, 0, 2, 2, out_b, 1.f, 0, 0, coords, 0, 0);
    mfn_fused<<<G,512,FUSED_SMEM>>>(net1_b, gabor_W, gabor_b, gabor_mu, gabor_ga, coords,
                                    fin_W, fin_b, out);
}

// round 15
// speedup vs baseline: 1.1398x; 1.1398x over previous
#include <cuda_runtime.h>
#include <cuda_bf16.h>
#include <math.h>
#include <stdint.h>

#define BATCH 8
#define NPTS  16384
#define M_KV  64
#define TOTM  (BATCH*NPTS)
#define P     16
#define PP    20
typedef unsigned long long ull;

// ======== PTX helpers ========
__device__ __forceinline__ uint32_t smem_u32(const void* p) {
    uint32_t a;
    asm("{ .reg .u64 t; cvta.to.shared.u64 t, %1; cvt.u32.u64 %0, t; }" : "=r"(a) : "l"(p));
    return a;
}
#define CP16(dst, src) asm volatile("cp.async.cg.shared.global [%0], [%1], 16;" :: "r"(dst), "l"(src) : "memory")
#define CP_COMMIT()    asm volatile("cp.async.commit_group;" ::: "memory")
#define CP_WAIT0()     asm volatile("cp.async.wait_group 0;" ::: "memory")
__device__ __forceinline__ void ldsm4(uint32_t* r, uint32_t addr) {
    asm volatile("ldmatrix.sync.aligned.m8n8.x4.shared.b16 {%0,%1,%2,%3}, [%4];"
        : "=r"(r[0]), "=r"(r[1]), "=r"(r[2]), "=r"(r[3]) : "r"(addr));
}
__device__ __forceinline__ void mma16816(float* c, const uint32_t* a, uint32_t b0, uint32_t b1) {
    asm volatile("mma.sync.aligned.m16n8k16.row.col.f32.bf16.bf16.f32 "
        "{%0,%1,%2,%3}, {%4,%5,%6,%7}, {%8,%9}, {%0,%1,%2,%3};"
        : "+f"(c[0]), "+f"(c[1]), "+f"(c[2]), "+f"(c[3])
        : "r"(a[0]), "r"(a[1]), "r"(a[2]), "r"(a[3]), "r"(b0), "r"(b1));
}
#define SW64(o) ((o) ^ (((o) >> 3) & 0x30))
__device__ __forceinline__ void fma2(ull& a, ull x, ull w) {
    asm("fma.rn.f32x2 %0, %1, %2, %0;" : "+l"(a) : "l"(x), "l"(w));
}
__device__ __forceinline__ float fold2(ull v) { float lo,hi; asm("mov.b64 {%0,%1}, %2;" : "=f"(lo),"=f"(hi) : "l"(v)); return lo+hi; }
__device__ __forceinline__ void unpack2(ull v, float& lo, float& hi) { asm("mov.b64 {%0,%1}, %2;" : "=f"(lo),"=f"(hi) : "l"(v)); }
__device__ __forceinline__ ull pack2(float lo, float hi) { ull r; asm("mov.b64 %0, {%1,%2};" : "=l"(r) : "f"(lo),"f"(hi)); return r; }
__device__ __forceinline__ uint32_t packbf(float v0, float v1, float& r0, float& r1) {
    __nv_bfloat16 h0 = __float2bfloat16_rn(v0);
    __nv_bfloat16 h1 = __float2bfloat16_rn(v1);
    r0 = v0 - __bfloat162float(h0);
    r1 = v1 - __bfloat162float(h1);
    unsigned short a = *(unsigned short*)&h0, b = *(unsigned short*)&h1;
    return (uint32_t)a | ((uint32_t)b << 16);
}
__device__ __forceinline__ uint32_t packlo(float l0, float l1) {
    __nv_bfloat16 a = __float2bfloat16_rn(l0);
    __nv_bfloat16 b = __float2bfloat16_rn(l1);
    unsigned short x = *(unsigned short*)&a, y = *(unsigned short*)&b;
    return (uint32_t)x | ((uint32_t)y << 16);
}

// ======== global scratch ========
#define SZ ((size_t)TOTM * 256)
__device__ __nv_bfloat16 g_X0h[SZ], g_X0l[SZ], g_X1h[SZ], g_X1l[SZ], g_Z2h[SZ], g_Z2l[SZ];
__device__ float g_Q[SZ];
__device__ __nv_bfloat16 g_Bh[12*65536], g_Bl[12*65536];
__device__ float g_WkT[65536], g_WvT[65536];
__device__ float g_Kt[BATCH*8*32*M_KV];
__device__ float g_Vt[BATCH*32*256*2];
__device__ __forceinline__ __nv_bfloat16* selH(int s){ return s==0?g_X0h:(s==1?g_X1h:g_Z2h); }
__device__ __forceinline__ __nv_bfloat16* selL(int s){ return s==0?g_X0l:(s==1?g_X1l:g_Z2l); }

// ======== prep kernels ========
__global__ void conv_w(const float* __restrict__ qp_W2, const float* __restrict__ in_W,
                       const float* __restrict__ out_W, const float* __restrict__ net2_W,
                       const float* __restrict__ net1_W) {
    int n = blockIdx.x, mat = blockIdx.y, k = threadIdx.x;
    if (mat >= 12) {
        const float* src = in_W + (size_t)(mat == 12 ? 256 : 512) * 256;
        float* dst = (mat == 12) ? g_WkT : g_WvT;
        dst[k*256 + n] = src[n*256 + k];
        return;
    }
    const float* src;
    switch (mat) {
        case 0: src = qp_W2; break;
        case 1: src = in_W;  break;
        case 2: src = out_W; break;
        default: src = (mat < 8) ? net2_W + (mat-3)*65536 : net1_W + (mat-8)*65536;
    }
    float w = src[n*256 + k];
    __nv_bfloat16 h = __float2bfloat16_rn(w);
    g_Bh[mat*65536 + n*256 + k] = h;
    g_Bl[mat*65536 + n*256 + k] = __float2bfloat16_rn(w - __bfloat162float(h));
}

__global__ void kv_kernel(const float* __restrict__ z_multi,
                          const float* __restrict__ lnkv_g, const float* __restrict__ lnkv_b,
                          const float* __restrict__ in_b) {
    __shared__ float kvn[8][256];
    int t = threadIdx.x, lane = t & 31, w = t >> 5;
    int row0 = blockIdx.x * 8;
    {
        int row = row0 + w;
        float v[8];
        float s = 0.f, ss = 0.f;
        #pragma unroll
        for (int j = 0; j < 8; ++j) {
            v[j] = z_multi[(size_t)row*256 + lane*8 + j];
            s += v[j]; ss += v[j]*v[j];
        }
        #pragma unroll
        for (int o = 16; o; o >>= 1) {
            s  += __shfl_xor_sync(0xffffffffu, s,  o);
            ss += __shfl_xor_sync(0xffffffffu, ss, o);
        }
        float mu = s * (1.f/256.f);
        float rstd = rsqrtf(ss * (1.f/256.f) - mu*mu + 1e-5f);
        #pragma unroll
        for (int j = 0; j < 8; ++j) {
            int d = lane*8 + j;
            kvn[w][d] = (v[j] - mu) * rstd * lnkv_g[d] + lnkv_b[d];
        }
    }
    __syncthreads();
    float aK[8], aV[8];
    float bK = in_b[256+t], bV = in_b[512+t];
    #pragma unroll
    for (int i = 0; i < 8; ++i) { aK[i] = bK; aV[i] = bV; }
    #pragma unroll 4
    for (int d = 0; d < 256; ++d) {
        float wk = g_WkT[d*256 + t];
        float wv = g_WvT[d*256 + t];
        #pragma unroll
        for (int i = 0; i < 8; ++i) {
            float x = kvn[i][d];
            aK[i] += x * wk;
            aV[i] += x * wv;
        }
    }
    #pragma unroll
    for (int i = 0; i < 8; ++i) {
        int row = row0 + i, b = row >> 6, m = row & 63;
        g_Kt[((b*8 + (t>>5))*32 + (t&31))*M_KV + m] = aK[i];
        g_Vt[((b*32 + (m>>1))*256 + t)*2 + (m&1)] = aV[i];
    }
}

// ======== warp-MMA GEMM (templated mode), stage-paired double buffer ========
#define OFF_AL 8192u
#define OFF_BH 16384u
#define OFF_BL 32768u
#define SLAB_BYTES 49152u
#define STAGE_BYTES 98304u
#define GEMM_SMEM (2*98304)
#define MODE_LN 0
#define MODE_Q 1
#define MODE_BIAS 2

template<bool COMPUTE_A>
__device__ __forceinline__ void load_chunk(uint32_t base,
        const __nv_bfloat16* AH, const __nv_bfloat16* AL,
        const __nv_bfloat16* BH, const __nv_bfloat16* BL,
        int m0, int c, int tid,
        float cxp, float cyp,
        const float* __restrict__ qpW1, const float* __restrict__ qpb1) {
    int r = tid >> 2, seg = tid & 3;
    uint32_t sA = base + SW64((uint32_t)(r*64 + seg*16));
    if (COMPUTE_A) {
        int h0 = c*32 + seg*8;
        #pragma unroll
        for (int j2 = 0; j2 < 4; ++j2) {
            int h = h0 + j2*2;
            float4 wv = *(const float4*)(qpW1 + 2*h);
            float2 bv = *(const float2*)(qpb1 + h);
            float u0 = wv.x*cxp + wv.y*cyp + bv.x;
            float u1 = wv.z*cxp + wv.w*cyp + bv.y;
            float v0 = 0.5f*u0*(1.f + erff(u0*0.70710678118654752f));
            float v1 = 0.5f*u1*(1.f + erff(u1*0.70710678118654752f));
            float l0, l1;
            uint32_t hp = packbf(v0, v1, l0, l1);
            uint32_t lp = packlo(l0, l1);
            asm volatile("st.shared.b32 [%0], %1;" :: "r"(sA + j2*4), "r"(hp) : "memory");
            asm volatile("st.shared.b32 [%0], %1;" :: "r"(sA + OFF_AL + j2*4), "r"(lp) : "memory");
        }
    } else {
        size_t aofs = (size_t)(m0 + r)*256 + c*32 + seg*8;
        CP16(sA, AH + aofs);
        CP16(sA + OFF_AL, AL + aofs);
    }
    #pragma unroll
    for (int it = 0; it < 2; ++it) {
        int row = r + it*128;
        size_t bofs = (size_t)row*256 + c*32 + seg*8;
        uint32_t sB = base + OFF_BH + SW64((uint32_t)(row*64 + seg*16));
        CP16(sB, BH + bofs);
        CP16(sB + 16384u, BL + bofs);
    }
}

template<int MODE>
__global__ void __launch_bounds__(512, 1)
gemm_mma(int nsrc, int srcA1, int matB1, int dst,
         const float* __restrict__ bias, float scale,
         const float* __restrict__ lng, const float* __restrict__ lnb,
         const float* __restrict__ coords,
         const float* __restrict__ qpW1, const float* __restrict__ qpb1) {
    extern __shared__ char smraw[];
    uint32_t sb = smem_u32(smraw);
    int tid = threadIdx.x, lane = tid & 31, w = tid >> 5;
    int wn = w & 3, wm = w >> 2;
    int m_block = blockIdx.x * 128;

    const __nv_bfloat16* AH = selH(srcA1);
    const __nv_bfloat16* AL = selL(srcA1);
    const __nv_bfloat16* BH = g_Bh + (size_t)matB1*65536;
    const __nv_bfloat16* BL = g_Bl + (size_t)matB1*65536;

    float cxp = 0.f, cyp = 0.f;
    if (MODE == MODE_LN) {
        float2 xy = *(const float2*)(coords + 2*(m_block + (tid >> 2)));
        cxp = xy.x; cyp = xy.y;
    }
    constexpr bool CA = (MODE == MODE_LN);

    int sub = lane & 7, blk = lane >> 3;
    int rowoff = sub + ((blk & 1) << 3);
    uint32_t koffB = (uint32_t)((blk >> 1) << 4);
    uint32_t aoff[2][2], boff[4][2];
    #pragma unroll
    for (int mt = 0; mt < 2; ++mt)
        #pragma unroll
        for (int kh = 0; kh < 2; ++kh)
            aoff[mt][kh] = SW64((uint32_t)((wm*32 + mt*16 + rowoff)*64 + kh*32) + koffB);
    #pragma unroll
    for (int ng = 0; ng < 4; ++ng)
        #pragma unroll
        for (int kh = 0; kh < 2; ++kh)
            boff[ng][kh] = SW64((uint32_t)((wn*64 + ng*16 + rowoff)*64 + kh*32) + koffB);

    float c[2][8][4];
    #pragma unroll
    for (int mt = 0; mt < 2; ++mt)
        #pragma unroll
        for (int nt = 0; nt < 8; ++nt)
            #pragma unroll
            for (int i = 0; i < 4; ++i) c[mt][nt][i] = 0.f;

    int nst = nsrc * 4;
    load_chunk<CA>(sb, AH, AL, BH, BL, m_block, 0, tid, cxp, cyp, qpW1, qpb1);
    load_chunk<CA>(sb + SLAB_BYTES, AH, AL, BH, BL, m_block, 1, tid, cxp, cyp, qpW1, qpb1);
    CP_COMMIT();

    for (int st = 0; st < nst; ++st) {
        CP_WAIT0();
        __syncthreads();
        if (st + 1 < nst) {
            int g = 2*(st+1), cc = g & 7;
            uint32_t nb = sb + ((st+1) & 1)*STAGE_BYTES;
            load_chunk<CA>(nb, AH, AL, BH, BL, m_block, cc, tid, cxp, cyp, qpW1, qpb1);
            load_chunk<CA>(nb + SLAB_BYTES, AH, AL, BH, BL, m_block, cc+1, tid, cxp, cyp, qpW1, qpb1);
            CP_COMMIT();
        }
        uint32_t stbase = sb + (st & 1)*STAGE_BYTES;
        #pragma unroll
        for (int sl = 0; sl < 2; ++sl) {
            uint32_t base = stbase + sl*SLAB_BYTES;
            #pragma unroll
            for (int kh = 0; kh < 2; ++kh) {
                uint32_t ah[2][4], al[2][4];
                ldsm4(ah[0], base + aoff[0][kh]);
                ldsm4(ah[1], base + aoff[1][kh]);
                ldsm4(al[0], base + OFF_AL + aoff[0][kh]);
                ldsm4(al[1], base + OFF_AL + aoff[1][kh]);
                #pragma unroll
                for (int ng = 0; ng < 4; ++ng) {
                    uint32_t bh[4], bl[4];
                    ldsm4(bh, base + OFF_BH + boff[ng][kh]);
                    ldsm4(bl, base + OFF_BL + boff[ng][kh]);
                    #pragma unroll
                    for (int mt = 0; mt < 2; ++mt) {
                        mma16816(c[mt][2*ng],   ah[mt], bh[0], bh[2]);
                        mma16816(c[mt][2*ng+1], ah[mt], bh[1], bh[3]);
                        mma16816(c[mt][2*ng],   al[mt], bh[0], bh[2]);
                        mma16816(c[mt][2*ng+1], al[mt], bh[1], bh[3]);
                        mma16816(c[mt][2*ng],   ah[mt], bl[0], bl[2]);
                        mma16816(c[mt][2*ng+1], ah[mt], bl[1], bl[3]);
                    }
                }
            }
        }
    }
    __syncthreads();

    // ======== fragment-direct epilogue ========
    float* sLN  = (float*)smraw;
    float* sLN2 = sLN + 512;
    int r4 = lane >> 2, kp2 = (lane & 3)*2;

    if (bias) {
        #pragma unroll
        for (int nt = 0; nt < 8; ++nt) {
            float2 bv = *(const float2*)(bias + wn*64 + nt*8 + kp2);
            #pragma unroll
            for (int mt = 0; mt < 2; ++mt) {
                c[mt][nt][0] += bv.x; c[mt][nt][1] += bv.y;
                c[mt][nt][2] += bv.x; c[mt][nt][3] += bv.y;
            }
        }
    }

    float muv[2][2], rsv[2][2];
    if (MODE == MODE_LN) {
        #pragma unroll
        for (int mt = 0; mt < 2; ++mt)
            #pragma unroll
            for (int hf = 0; hf < 2; ++hf) {
                float s = 0.f, ss = 0.f;
                #pragma unroll
                for (int nt = 0; nt < 8; ++nt) {
                    float v0 = c[mt][nt][2*hf], v1 = c[mt][nt][2*hf+1];
                    s += v0 + v1; ss += v0*v0 + v1*v1;
                }
                s  += __shfl_xor_sync(0xffffffffu, s, 1);  s += __shfl_xor_sync(0xffffffffu, s, 2);
                ss += __shfl_xor_sync(0xffffffffu, ss, 1); ss += __shfl_xor_sync(0xffffffffu, ss, 2);
                if ((lane & 3) == 0) {
                    int rl = wm*32 + mt*16 + hf*8 + r4;
                    sLN[rl*4 + wn] = s; sLN2[rl*4 + wn] = ss;
                }
            }
        __syncthreads();
        #pragma unroll
        for (int mt = 0; mt < 2; ++mt)
            #pragma unroll
            for (int hf = 0; hf < 2; ++hf) {
                int rl = wm*32 + mt*16 + hf*8 + r4;
                float S  = sLN[rl*4]  + sLN[rl*4+1]  + sLN[rl*4+2]  + sLN[rl*4+3];
                float SS = sLN2[rl*4] + sLN2[rl*4+1] + sLN2[rl*4+2] + sLN2[rl*4+3];
                float mu = S * (1.f/256.f);
                muv[mt][hf] = mu;
                rsv[mt][hf] = rsqrtf(SS * (1.f/256.f) - mu*mu + 1e-5f);
            }
    }

    __nv_bfloat16* oH = selH(dst);
    __nv_bfloat16* oL = selL(dst);
    #pragma unroll
    for (int nt = 0; nt < 8; ++nt) {
        int col = wn*64 + nt*8 + kp2;
        float lg0 = 0.f, lg1 = 0.f, lb0 = 0.f, lb1 = 0.f;
        if (MODE == MODE_LN) {
            float2 lg = *(const float2*)(lng + col);
            float2 lb = *(const float2*)(lnb + col);
            lg0 = lg.x; lg1 = lg.y; lb0 = lb.x; lb1 = lb.y;
        }
        #pragma unroll
        for (int mt = 0; mt < 2; ++mt)
            #pragma unroll
            for (int hf = 0; hf < 2; ++hf) {
                int pt = m_block + wm*32 + mt*16 + hf*8 + r4;
                float v0 = c[mt][nt][2*hf], v1 = c[mt][nt][2*hf+1];
                if (MODE == MODE_LN) {
                    v0 = (v0 - muv[mt][hf]) * rsv[mt][hf] * lg0 + lb0;
                    v1 = (v1 - muv[mt][hf]) * rsv[mt][hf] * lg1 + lb1;
                }
                if (MODE == MODE_Q) {
                    *(float2*)(g_Q + (size_t)pt*256 + col) = make_float2(v0*scale, v1*scale);
                } else {
                    float l0, l1;
                    uint32_t hp = packbf(v0, v1, l0, l1);
                    uint32_t lp = packlo(l0, l1);
                    *(uint32_t*)(oH + (size_t)pt*256 + col) = hp;
                    *(uint32_t*)(oL + (size_t)pt*256 + col) = lp;
                }
            }
    }
}

// ======== fused MFN kernel: L0..L4 + fragment-direct fin + irfft ========
#define FX_BYTES 131072u
#define FSLAB 49152u
#define FUSED_SMEM (131072 + 2*49152)

__global__ void __launch_bounds__(512, 1)
mfn_fused(const float* __restrict__ net1_b,
          const float* __restrict__ gW, const float* __restrict__ gb,
          const float* __restrict__ gmu, const float* __restrict__ gga,
          const float* __restrict__ coords,
          const float* __restrict__ fin_W, const float* __restrict__ fin_b,
          float* __restrict__ out) {
    extern __shared__ char smraw[];
    uint32_t sb = smem_u32(smraw);
    uint32_t stoff = sb + FX_BYTES;
    int tid = threadIdx.x, lane = tid & 31, w = tid >> 5;
    int wn = w & 3, wm = w >> 2;
    int m_block = blockIdx.x * 128;

    int sub = lane & 7, blk = lane >> 3;
    int rowoff = sub + ((blk & 1) << 3);
    uint32_t koffB = (uint32_t)((blk >> 1) << 4);
    uint32_t aoff[2][2], boff[4][2];
    #pragma unroll
    for (int mt = 0; mt < 2; ++mt)
        #pragma unroll
        for (int kh = 0; kh < 2; ++kh)
            aoff[mt][kh] = SW64((uint32_t)((wm*32 + mt*16 + rowoff)*64 + kh*32) + koffB);
    #pragma unroll
    for (int ng = 0; ng < 4; ++ng)
        #pragma unroll
        for (int kh = 0; kh < 2; ++kh)
            boff[ng][kh] = SW64((uint32_t)((wn*64 + ng*16 + rowoff)*64 + kh*32) + koffB);

    int r4 = lane >> 2, kp2 = (lane & 3)*2;
    float cx[2][2], cy[2][2], rr2[2][2];
    #pragma unroll
    for (int mt = 0; mt < 2; ++mt)
        #pragma unroll
        for (int hf = 0; hf < 2; ++hf) {
            int pt = m_block + wm*32 + mt*16 + hf*8 + r4;
            float2 xy = *(const float2*)(coords + 2*pt);
            cx[mt][hf] = xy.x; cy[mt][hf] = xy.y; rr2[mt][hf] = xy.x*xy.x + xy.y*xy.y;
        }

    auto prefetch = [&](int L, int i, uint32_t stb) {
        bool loadA; int ch, matB;
        if (L == 0)      { loadA = true;  ch = i;     matB = 3; }
        else if (i < 8)  { loadA = false; ch = i;     matB = 8 + (L-1); }
        else             { loadA = true;  ch = i - 8; matB = 3 + L; }
        const __nv_bfloat16* BHp = g_Bh + (size_t)matB*65536;
        const __nv_bfloat16* BLp = g_Bl + (size_t)matB*65536;
        int r = tid >> 2, seg = tid & 3;
        size_t go = (size_t)ch*32 + seg*8;
        if (loadA) {
            size_t aofs = (size_t)(m_block + r)*256 + go;
            uint32_t sA = stb + SW64((uint32_t)(r*64 + seg*16));
            CP16(sA, g_Z2h + aofs);
            CP16(sA + OFF_AL, g_Z2l + aofs);
        }
        #pragma unroll
        for (int it = 0; it < 2; ++it) {
            int row = r + it*128;
            uint32_t sB = stb + OFF_BH + SW64((uint32_t)(row*64 + seg*16));
            CP16(sB, BHp + (size_t)row*256 + go);
            CP16(sB + 16384u, BLp + (size_t)row*256 + go);
        }
    };

    float c[2][8][4];
    int s = 0;
    prefetch(0, 0, stoff);
    CP_COMMIT();

    for (int L = 0; L <= 4; ++L) {
        int np = (L == 0) ? 8 : 16;
        #pragma unroll
        for (int mt = 0; mt < 2; ++mt)
            #pragma unroll
            for (int nt = 0; nt < 8; ++nt)
                #pragma unroll
                for (int i = 0; i < 4; ++i) c[mt][nt][i] = 0.f;

        for (int i = 0; i < np; ++i) {
            CP_WAIT0();
            __syncthreads();
            {
                int nL = L, ni = i + 1;
                if (ni == np) { nL = L + 1; ni = 0; }
                if (nL <= 4) {
                    prefetch(nL, ni, stoff + (uint32_t)((s+1) & 1)*FSLAB);
                    CP_COMMIT();
                }
            }
            bool isx = (L > 0 && i < 8);
            uint32_t stb = stoff + (uint32_t)(s & 1)*FSLAB;
            uint32_t Abase = isx ? (sb + (uint32_t)i*16384u) : stb;
            uint32_t Bbase = stb;
            #pragma unroll
            for (int kh = 0; kh < 2; ++kh) {
                uint32_t ah[2][4], al[2][4];
                ldsm4(ah[0], Abase + aoff[0][kh]);
                ldsm4(ah[1], Abase + aoff[1][kh]);
                ldsm4(al[0], Abase + OFF_AL + aoff[0][kh]);
                ldsm4(al[1], Abase + OFF_AL + aoff[1][kh]);
                #pragma unroll
                for (int ng = 0; ng < 4; ++ng) {
                    uint32_t bh[4], bl[4];
                    ldsm4(bh, Bbase + OFF_BH + boff[ng][kh]);
                    ldsm4(bl, Bbase + OFF_BL + boff[ng][kh]);
                    #pragma unroll
                    for (int mt = 0; mt < 2; ++mt) {
                        mma16816(c[mt][2*ng],   ah[mt], bh[0], bh[2]);
                        mma16816(c[mt][2*ng+1], ah[mt], bh[1], bh[3]);
                        mma16816(c[mt][2*ng],   al[mt], bh[0], bh[2]);
                        mma16816(c[mt][2*ng+1], al[mt], bh[1], bh[3]);
                        mma16816(c[mt][2*ng],   ah[mt], bl[0], bl[2]);
                        mma16816(c[mt][2*ng+1], ah[mt], bl[1], bl[3]);
                    }
                }
            }
            ++s;
        }
        __syncthreads();   // all reads of x done before overwrite

        // ---- epilogue layer L: bias + gabor; L<4 -> write x to smem; L==4 -> keep in c ----
        #pragma unroll
        for (int nt = 0; nt < 8; ++nt) {
            int col = wn*64 + nt*8 + kp2;
            if (L > 0) {
                float2 bv = *(const float2*)(net1_b + (L-1)*256 + col);
                #pragma unroll
                for (int mt = 0; mt < 2; ++mt) {
                    c[mt][nt][0] += bv.x; c[mt][nt][1] += bv.y;
                    c[mt][nt][2] += bv.x; c[mt][nt][3] += bv.y;
                }
            }
            int idx = L*256 + col;
            float4 wv = *(const float4*)(gW + 2*idx);
            float4 mv = *(const float4*)(gmu + 2*idx);
            float2 bb = *(const float2*)(gb + idx);
            float2 gv = *(const float2*)(gga + idx);
            float mu20 = mv.x*mv.x + mv.y*mv.y;
            float mu21 = mv.z*mv.z + mv.w*mv.w;
            #pragma unroll
            for (int mt = 0; mt < 2; ++mt)
                #pragma unroll
                for (int hf = 0; hf < 2; ++hf) {
                    float x = cx[mt][hf], y = cy[mt][hf], r2 = rr2[mt][hf];
                    float D0 = r2 + mu20 - 2.f*(x*mv.x + y*mv.y);
                    float D1 = r2 + mu21 - 2.f*(x*mv.z + y*mv.w);
                    float v0 = c[mt][nt][2*hf]   * (sinf(wv.x*x + wv.y*y + bb.x) * __expf(-0.5f*D0*gv.x));
                    float v1 = c[mt][nt][2*hf+1] * (sinf(wv.z*x + wv.w*y + bb.y) * __expf(-0.5f*D1*gv.y));
                    if (L < 4) {
                        float l0, l1;
                        uint32_t hp = packbf(v0, v1, l0, l1);
                        uint32_t lp = packlo(l0, l1);
                        int rl = wm*32 + mt*16 + hf*8 + r4;
                        uint32_t xo = sb + (uint32_t)(col >> 5)*16384u
                                    + SW64((uint32_t)(rl*64 + (col & 31)*2));
                        asm volatile("st.shared.b32 [%0], %1;" :: "r"(xo), "r"(hp) : "memory");
                        asm volatile("st.shared.b32 [%0], %1;" :: "r"(xo + OFF_AL), "r"(lp) : "memory");
                    } else {
                        c[mt][nt][2*hf]   = v0;   // keep final x in fragments
                        c[mt][nt][2*hf+1] = v1;
                    }
                }
        }
    }
    __syncthreads();   // x-buffer smem now dead; alias for fin partials

    // ======== fragment-direct fin + irfft ========
    {
        float* sW   = (float*)smraw;           // [128][36][4]  (73728 B)
        float* sF   = sW + 128*36*4;           // [128][36]     (18432 B)
        float* sTab = sF + 128*36;             // [32]
        if (tid < 16) {
            float sv, cv;
            sincosf(0.39269908169872414f * (float)tid, &sv, &cv);
            sTab[2*tid] = cv; sTab[2*tid+1] = sv;
        }
        // per-warp partials: rows wm*32 + {0,8,16,24} + r4, cols wn*64..+63
        for (int g = 0; g < 36; ++g) {
            ull acc0 = 0ull, acc1 = 0ull, acc2 = 0ull, acc3 = 0ull;
            const float* Wg = fin_W + g*256 + wn*64 + kp2;
            #pragma unroll
            for (int nt = 0; nt < 8; ++nt) {
                float2 wvv = *(const float2*)(Wg + nt*8);
                ull wp = pack2(wvv.x, wvv.y);
                fma2(acc0, pack2(c[0][nt][0], c[0][nt][1]), wp);
                fma2(acc1, pack2(c[0][nt][2], c[0][nt][3]), wp);
                fma2(acc2, pack2(c[1][nt][0], c[1][nt][1]), wp);
                fma2(acc3, pack2(c[1][nt][2], c[1][nt][3]), wp);
            }
            float f0 = fold2(acc0), f1 = fold2(acc1), f2 = fold2(acc2), f3 = fold2(acc3);
            f0 += __shfl_xor_sync(0xffffffffu, f0, 1); f0 += __shfl_xor_sync(0xffffffffu, f0, 2);
            f1 += __shfl_xor_sync(0xffffffffu, f1, 1); f1 += __shfl_xor_sync(0xffffffffu, f1, 2);
            f2 += __shfl_xor_sync(0xffffffffu, f2, 1); f2 += __shfl_xor_sync(0xffffffffu, f2, 2);
            f3 += __shfl_xor_sync(0xffffffffu, f3, 1); f3 += __shfl_xor_sync(0xffffffffu, f3, 2);
            if ((lane & 3) == 0) {
                int rbase = wm*32 + r4;
                sW[(rbase     )*144 + g*4 + wn] = f0;
                sW[(rbase +  8)*144 + g*4 + wn] = f1;
                sW[(rbase + 16)*144 + g*4 + wn] = f2;
                sW[(rbase + 24)*144 + g*4 + wn] = f3;
            }
        }
        __syncthreads();
        // reduce 4 warp-partials + bias -> sF
        if (tid < 128) {
            const float* wp = sW + tid*144;
            #pragma unroll 4
            for (int g = 0; g < 36; ++g)
                sF[tid*36 + g] = wp[g*4] + wp[g*4+1] + wp[g*4+2] + wp[g*4+3] + fin_b[g];
        }
        __syncthreads();
        // irfft: 128 points x 2 ch x 16 t, 8 outputs per thread
        int pc = tid & 255;
        int pp2 = pc >> 1, ch = pc & 1;
        int tg = tid >> 8;
        const float* Fp = &sF[pp2*36];
        int b = m_block >> 14;
        int n0p = (m_block & (NPTS-1)) + pp2;
        #pragma unroll
        for (int it = 0; it < 8; ++it) {
            int tt = tg + 2*it;
            float a = Fp[ch*2];
            float f8 = Fp[8*4 + ch*2];
            a += (tt & 1) ? -f8 : f8;
            #pragma unroll
            for (int fq = 1; fq < 8; ++fq) {
                float re = Fp[fq*4 + ch*2], im = Fp[fq*4 + ch*2 + 1];
                int k = (fq*tt) & 15;
                a += 2.f * (re*sTab[2*k] - im*sTab[2*k+1]);
            }
            out[(((b*16 + tt)*NPTS) + n0p)*2 + ch] = 0.25f * a;
        }
    }
}

// ======== attention (scalar) ========
#define ATTN_SMF (5120 + P*512)
__global__ void __launch_bounds__(256, 2) attn_kernel() {
    extern __shared__ float smf[];
    float* sA = smf;
    float* sS = sA + 5120;
    int t = threadIdx.x, lane = t & 31, w = t >> 5;
    int bid = blockIdx.x, b = bid >> 10, n0 = (bid & 1023) * P;
    size_t base = (size_t)(b*NPTS + n0) * 256;
    #pragma unroll
    for (int p = 0; p < P; ++p) sA[t*PP + p] = g_Q[base + (size_t)p*256 + t];
    __syncthreads();
    #pragma unroll
    for (int rep = 0; rep < 2; ++rep) {
        int pair = t + rep*256, hh = pair >> 6, m = pair & 63;
        const float* Kp = &g_Kt[((b*8 + hh)*32)*M_KV + m];
        ull a2[8];
        #pragma unroll
        for (int j = 0; j < 8; ++j) a2[j] = 0ull;
        #pragma unroll 4
        for (int k = 0; k < 32; ++k) {
            float kv = Kp[k*M_KV];
            ull kk = pack2(kv, kv);
            const ulonglong2* col = (const ulonglong2*)(sA + (hh*32 + k)*PP);
            #pragma unroll
            for (int q = 0; q < 4; ++q) { ulonglong2 x = col[q]; fma2(a2[2*q], x.x, kk); fma2(a2[2*q+1], x.y, kk); }
        }
        #pragma unroll
        for (int j = 0; j < 8; ++j) {
            float lo, hi; unpack2(a2[j], lo, hi);
            sS[(2*j)*512 + pair] = lo; sS[(2*j+1)*512 + pair] = hi;
        }
    }
    __syncthreads();
    for (int rr = 0; rr < 16; ++rr) {
        int r = w + rr*8, p = r >> 3, hh = r & 7;
        float* bs = &sS[p*512 + hh*64];
        float v0 = bs[lane], v1 = bs[lane+32];
        float mx = fmaxf(v0, v1);
        #pragma unroll
        for (int o = 16; o; o >>= 1) mx = fmaxf(mx, __shfl_xor_sync(0xffffffffu, mx, o));
        float e0 = __expf(v0-mx), e1 = __expf(v1-mx), sum = e0 + e1;
        #pragma unroll
        for (int o = 16; o; o >>= 1) sum += __shfl_xor_sync(0xffffffffu, sum, o);
        float inv = 1.f/sum;
        bs[lane] = e0*inv; bs[lane+32] = e1*inv;
    }
    __syncthreads();
    {
        int hh = t >> 5;
        ull acc[P];
        #pragma unroll
        for (int p = 0; p < P; ++p) acc[p] = 0ull;
        const float* Vb = g_Vt + b*32*512;
        #pragma unroll 2
        for (int m = 0; m < M_KV; m += 2) {
            ull vv = *(const ull*)(Vb + ((m>>1)*256 + t)*2);
            #pragma unroll
            for (int p = 0; p < P; ++p) fma2(acc[p], *(const ull*)(&sS[p*512 + hh*64 + m]), vv);
        }
        #pragma unroll
        for (int p = 0; p < P; ++p) {
            float v = fold2(acc[p]);
            __nv_bfloat16 h = __float2bfloat16_rn(v);
            g_X0h[base + (size_t)p*256 + t] = h;
            g_X0l[base + (size_t)p*256 + t] = __float2bfloat16_rn(v - __bfloat162float(h));
        }
    }
}

// ======== launch ========
extern "C" void kernel_launch(void* const* d_in, const int* in_sizes, int n_in,
                              void* d_out, int out_size) {
    const float* z_multi=(const float*)d_in[0];  const float* coords=(const float*)d_in[1];
    const float* gabor_W=(const float*)d_in[2];  const float* gabor_b=(const float*)d_in[3];
    const float* gabor_mu=(const float*)d_in[4]; const float* gabor_ga=(const float*)d_in[5];
    const float* net1_W=(const float*)d_in[6];   const float* net1_b=(const float*)d_in[7];
    const float* net2_W=(const float*)d_in[8];   const float* qp_W1=(const float*)d_in[9];
    const float* qp_b1=(const float*)d_in[10];   const float* qp_W2=(const float*)d_in[11];
    const float* qp_b2=(const float*)d_in[12];   const float* in_W=(const float*)d_in[13];
    const float* in_b=(const float*)d_in[14];    const float* out_W=(const float*)d_in[15];
    const float* out_b=(const float*)d_in[16];   const float* lnq_g=(const float*)d_in[17];
    const float* lnq_b=(const float*)d_in[18];   const float* lnkv_g=(const float*)d_in[19];
    const float* lnkv_b=(const float*)d_in[20];  const float* fin_W=(const float*)d_in[21];
    const float* fin_b=(const float*)d_in[22];
    float* out = (float*)d_out;

    cudaFuncSetAttribute(gemm_mma<MODE_LN>,   cudaFuncAttributeMaxDynamicSharedMemorySize, GEMM_SMEM);
    cudaFuncSetAttribute(gemm_mma<MODE_Q>,    cudaFuncAttributeMaxDynamicSharedMemorySize, GEMM_SMEM);
    cudaFuncSetAttribute(gemm_mma<MODE_BIAS>, cudaFuncAttributeMaxDynamicSharedMemorySize, GEMM_SMEM);
    cudaFuncSetAttribute(mfn_fused,           cudaFuncAttributeMaxDynamicSharedMemorySize, FUSED_SMEM);
    cudaFuncSetAttribute(attn_kernel, cudaFuncAttributeMaxDynamicSharedMemorySize, ATTN_SMF*4);

    conv_w<<<dim3(256,14), 256>>>(qp_W2, in_W, out_W, net2_W, net1_W);
    kv_kernel<<<BATCH*M_KV/8, 256>>>(z_multi, lnkv_g, lnkv_b, in_b);

    int G = TOTM/128;
    const float qscale = 0.17677669529663687f;  // 1/sqrt(32)
    gemm_mma<MODE_LN><<<G,512,GEMM_SMEM>>>(1, 0, 0, 1, qp_b2, 1.f, lnq_g, lnq_b, coords, qp_W1, qp_b1);
    gemm_mma<MODE_Q><<<G,512,GEMM_SMEM>>>(1, 1, 1, 0, in_b, qscale, 0, 0, coords, 0, 0);
    attn_kernel<<<BATCH*(NPTS/P), 256, ATTN_SMF*4>>>();
    gemm_mma<MODE_BIAS><<<G,512,GEMM_SMEM>>>(1, 0, 2, 2, out_b, 1.f, 0, 0, coords, 0, 0);
    mfn_fused<<<G,512,FUSED_SMEM>>>(net1_b, gabor_W, gabor_b, gabor_mu, gabor_ga, coords,
                                    fin_W, fin_b, out);
}

// round 16
// speedup vs baseline: 1.1759x; 1.0316x over previous
#include <cuda_runtime.h>
#include <cuda_bf16.h>
#include <math.h>
#include <stdint.h>

#define BATCH 8
#define NPTS  16384
#define M_KV  64
#define TOTM  (BATCH*NPTS)
#define P     16
#define PP    20
typedef unsigned long long ull;

// ======== PTX helpers ========
__device__ __forceinline__ uint32_t smem_u32(const void* p) {
    uint32_t a;
    asm("{ .reg .u64 t; cvta.to.shared.u64 t, %1; cvt.u32.u64 %0, t; }" : "=r"(a) : "l"(p));
    return a;
}
#define CP16(dst, src) asm volatile("cp.async.cg.shared.global [%0], [%1], 16;" :: "r"(dst), "l"(src) : "memory")
#define CP_COMMIT()    asm volatile("cp.async.commit_group;" ::: "memory")
#define CP_WAIT0()     asm volatile("cp.async.wait_group 0;" ::: "memory")
__device__ __forceinline__ void ldsm4(uint32_t* r, uint32_t addr) {
    asm volatile("ldmatrix.sync.aligned.m8n8.x4.shared.b16 {%0,%1,%2,%3}, [%4];"
        : "=r"(r[0]), "=r"(r[1]), "=r"(r[2]), "=r"(r[3]) : "r"(addr));
}
__device__ __forceinline__ void mma16816(float* c, const uint32_t* a, uint32_t b0, uint32_t b1) {
    asm volatile("mma.sync.aligned.m16n8k16.row.col.f32.bf16.bf16.f32 "
        "{%0,%1,%2,%3}, {%4,%5,%6,%7}, {%8,%9}, {%0,%1,%2,%3};"
        : "+f"(c[0]), "+f"(c[1]), "+f"(c[2]), "+f"(c[3])
        : "r"(a[0]), "r"(a[1]), "r"(a[2]), "r"(a[3]), "r"(b0), "r"(b1));
}
#define SW64(o) ((o) ^ (((o) >> 3) & 0x30))
__device__ __forceinline__ void fma2(ull& a, ull x, ull w) {
    asm("fma.rn.f32x2 %0, %1, %2, %0;" : "+l"(a) : "l"(x), "l"(w));
}
__device__ __forceinline__ float fold2(ull v) { float lo,hi; asm("mov.b64 {%0,%1}, %2;" : "=f"(lo),"=f"(hi) : "l"(v)); return lo+hi; }
__device__ __forceinline__ void unpack2(ull v, float& lo, float& hi) { asm("mov.b64 {%0,%1}, %2;" : "=f"(lo),"=f"(hi) : "l"(v)); }
__device__ __forceinline__ ull pack2(float lo, float hi) { ull r; asm("mov.b64 %0, {%1,%2};" : "=l"(r) : "f"(lo),"f"(hi)); return r; }
__device__ __forceinline__ uint32_t packbf(float v0, float v1, float& r0, float& r1) {
    __nv_bfloat16 h0 = __float2bfloat16_rn(v0);
    __nv_bfloat16 h1 = __float2bfloat16_rn(v1);
    r0 = v0 - __bfloat162float(h0);
    r1 = v1 - __bfloat162float(h1);
    unsigned short a = *(unsigned short*)&h0, b = *(unsigned short*)&h1;
    return (uint32_t)a | ((uint32_t)b << 16);
}
__device__ __forceinline__ uint32_t packlo(float l0, float l1) {
    __nv_bfloat16 a = __float2bfloat16_rn(l0);
    __nv_bfloat16 b = __float2bfloat16_rn(l1);
    unsigned short x = *(unsigned short*)&a, y = *(unsigned short*)&b;
    return (uint32_t)x | ((uint32_t)y << 16);
}

// ======== global scratch ========
#define SZ ((size_t)TOTM * 256)
__device__ __nv_bfloat16 g_X0h[SZ], g_X0l[SZ], g_Z2h[SZ], g_Z2l[SZ];
__device__ float g_Q[SZ];
__device__ __nv_bfloat16 g_Bh[12*65536], g_Bl[12*65536];
__device__ float g_WkT[65536], g_WvT[65536];
__device__ float g_Kt[BATCH*8*32*M_KV];
__device__ float g_Vt[BATCH*32*256*2];
__device__ __forceinline__ __nv_bfloat16* selH(int s){ return s==0?g_X0h:g_Z2h; }
__device__ __forceinline__ __nv_bfloat16* selL(int s){ return s==0?g_X0l:g_Z2l; }

// ======== prep kernels ========
__global__ void conv_w(const float* __restrict__ qp_W2, const float* __restrict__ in_W,
                       const float* __restrict__ out_W, const float* __restrict__ net2_W,
                       const float* __restrict__ net1_W) {
    int n = blockIdx.x, mat = blockIdx.y, k = threadIdx.x;
    if (mat >= 12) {
        const float* src = in_W + (size_t)(mat == 12 ? 256 : 512) * 256;
        float* dst = (mat == 12) ? g_WkT : g_WvT;
        dst[k*256 + n] = src[n*256 + k];
        return;
    }
    const float* src;
    switch (mat) {
        case 0: src = qp_W2; break;
        case 1: src = in_W;  break;
        case 2: src = out_W; break;
        default: src = (mat < 8) ? net2_W + (mat-3)*65536 : net1_W + (mat-8)*65536;
    }
    float w = src[n*256 + k];
    __nv_bfloat16 h = __float2bfloat16_rn(w);
    g_Bh[mat*65536 + n*256 + k] = h;
    g_Bl[mat*65536 + n*256 + k] = __float2bfloat16_rn(w - __bfloat162float(h));
}

__global__ void kv_kernel(const float* __restrict__ z_multi,
                          const float* __restrict__ lnkv_g, const float* __restrict__ lnkv_b,
                          const float* __restrict__ in_b) {
    __shared__ float kvn[8][256];
    int t = threadIdx.x, lane = t & 31, w = t >> 5;
    int row0 = blockIdx.x * 8;
    {
        int row = row0 + w;
        float v[8];
        float s = 0.f, ss = 0.f;
        #pragma unroll
        for (int j = 0; j < 8; ++j) {
            v[j] = z_multi[(size_t)row*256 + lane*8 + j];
            s += v[j]; ss += v[j]*v[j];
        }
        #pragma unroll
        for (int o = 16; o; o >>= 1) {
            s  += __shfl_xor_sync(0xffffffffu, s,  o);
            ss += __shfl_xor_sync(0xffffffffu, ss, o);
        }
        float mu = s * (1.f/256.f);
        float rstd = rsqrtf(ss * (1.f/256.f) - mu*mu + 1e-5f);
        #pragma unroll
        for (int j = 0; j < 8; ++j) {
            int d = lane*8 + j;
            kvn[w][d] = (v[j] - mu) * rstd * lnkv_g[d] + lnkv_b[d];
        }
    }
    __syncthreads();
    float aK[8], aV[8];
    float bK = in_b[256+t], bV = in_b[512+t];
    #pragma unroll
    for (int i = 0; i < 8; ++i) { aK[i] = bK; aV[i] = bV; }
    #pragma unroll 4
    for (int d = 0; d < 256; ++d) {
        float wk = g_WkT[d*256 + t];
        float wv = g_WvT[d*256 + t];
        #pragma unroll
        for (int i = 0; i < 8; ++i) {
            float x = kvn[i][d];
            aK[i] += x * wk;
            aV[i] += x * wv;
        }
    }
    #pragma unroll
    for (int i = 0; i < 8; ++i) {
        int row = row0 + i, b = row >> 6, m = row & 63;
        g_Kt[((b*8 + (t>>5))*32 + (t&31))*M_KV + m] = aK[i];
        g_Vt[((b*32 + (m>>1))*256 + t)*2 + (m&1)] = aV[i];
    }
}

// ======== common offsets ========
#define OFF_AL 8192u
#define OFF_BH 16384u
#define OFF_BL 32768u
#define SLAB_BYTES 49152u
#define STAGE_BYTES 98304u
#define GEMM_SMEM (2*98304)
#define MODE_BIAS 2

// ======== standalone GEMM (BIAS mode only: z = ctx @ outW^T + out_b) ========
__device__ __forceinline__ void load_chunk_g(uint32_t base,
        const __nv_bfloat16* AH, const __nv_bfloat16* AL,
        const __nv_bfloat16* BH, const __nv_bfloat16* BL,
        int m0, int c, int tid) {
    int r = tid >> 2, seg = tid & 3;
    size_t aofs = (size_t)(m0 + r)*256 + c*32 + seg*8;
    uint32_t sA = base + SW64((uint32_t)(r*64 + seg*16));
    CP16(sA, AH + aofs);
    CP16(sA + OFF_AL, AL + aofs);
    #pragma unroll
    for (int it = 0; it < 2; ++it) {
        int row = r + it*128;
        size_t bofs = (size_t)row*256 + c*32 + seg*8;
        uint32_t sB = base + OFF_BH + SW64((uint32_t)(row*64 + seg*16));
        CP16(sB, BH + bofs);
        CP16(sB + 16384u, BL + bofs);
    }
}

__global__ void __launch_bounds__(512, 1)
gemm_bias(int srcA1, int matB1, int dst, const float* __restrict__ bias) {
    extern __shared__ char smraw[];
    uint32_t sb = smem_u32(smraw);
    int tid = threadIdx.x, lane = tid & 31, w = tid >> 5;
    int wn = w & 3, wm = w >> 2;
    int m_block = blockIdx.x * 128;

    const __nv_bfloat16* AH = selH(srcA1);
    const __nv_bfloat16* AL = selL(srcA1);
    const __nv_bfloat16* BH = g_Bh + (size_t)matB1*65536;
    const __nv_bfloat16* BL = g_Bl + (size_t)matB1*65536;

    int sub = lane & 7, blk = lane >> 3;
    int rowoff = sub + ((blk & 1) << 3);
    uint32_t koffB = (uint32_t)((blk >> 1) << 4);
    uint32_t aoff[2][2], boff[4][2];
    #pragma unroll
    for (int mt = 0; mt < 2; ++mt)
        #pragma unroll
        for (int kh = 0; kh < 2; ++kh)
            aoff[mt][kh] = SW64((uint32_t)((wm*32 + mt*16 + rowoff)*64 + kh*32) + koffB);
    #pragma unroll
    for (int ng = 0; ng < 4; ++ng)
        #pragma unroll
        for (int kh = 0; kh < 2; ++kh)
            boff[ng][kh] = SW64((uint32_t)((wn*64 + ng*16 + rowoff)*64 + kh*32) + koffB);

    float c[2][8][4];
    #pragma unroll
    for (int mt = 0; mt < 2; ++mt)
        #pragma unroll
        for (int nt = 0; nt < 8; ++nt)
            #pragma unroll
            for (int i = 0; i < 4; ++i) c[mt][nt][i] = 0.f;

    load_chunk_g(sb, AH, AL, BH, BL, m_block, 0, tid);
    load_chunk_g(sb + SLAB_BYTES, AH, AL, BH, BL, m_block, 1, tid);
    CP_COMMIT();

    for (int st = 0; st < 4; ++st) {
        CP_WAIT0();
        __syncthreads();
        if (st + 1 < 4) {
            int g = 2*(st+1);
            uint32_t nb = sb + ((st+1) & 1)*STAGE_BYTES;
            load_chunk_g(nb, AH, AL, BH, BL, m_block, g, tid);
            load_chunk_g(nb + SLAB_BYTES, AH, AL, BH, BL, m_block, g+1, tid);
            CP_COMMIT();
        }
        uint32_t stbase = sb + (st & 1)*STAGE_BYTES;
        #pragma unroll
        for (int sl = 0; sl < 2; ++sl) {
            uint32_t base = stbase + sl*SLAB_BYTES;
            #pragma unroll
            for (int kh = 0; kh < 2; ++kh) {
                uint32_t ah[2][4], al[2][4];
                ldsm4(ah[0], base + aoff[0][kh]);
                ldsm4(ah[1], base + aoff[1][kh]);
                ldsm4(al[0], base + OFF_AL + aoff[0][kh]);
                ldsm4(al[1], base + OFF_AL + aoff[1][kh]);
                #pragma unroll
                for (int ng = 0; ng < 4; ++ng) {
                    uint32_t bh[4], bl[4];
                    ldsm4(bh, base + OFF_BH + boff[ng][kh]);
                    ldsm4(bl, base + OFF_BL + boff[ng][kh]);
                    #pragma unroll
                    for (int mt = 0; mt < 2; ++mt) {
                        mma16816(c[mt][2*ng],   ah[mt], bh[0], bh[2]);
                        mma16816(c[mt][2*ng+1], ah[mt], bh[1], bh[3]);
                        mma16816(c[mt][2*ng],   al[mt], bh[0], bh[2]);
                        mma16816(c[mt][2*ng+1], al[mt], bh[1], bh[3]);
                        mma16816(c[mt][2*ng],   ah[mt], bl[0], bl[2]);
                        mma16816(c[mt][2*ng+1], ah[mt], bl[1], bl[3]);
                    }
                }
            }
        }
    }
    __syncthreads();

    int r4 = lane >> 2, kp2 = (lane & 3)*2;
    __nv_bfloat16* oH = selH(dst);
    __nv_bfloat16* oL = selL(dst);
    #pragma unroll
    for (int nt = 0; nt < 8; ++nt) {
        int col = wn*64 + nt*8 + kp2;
        float2 bv = *(const float2*)(bias + col);
        #pragma unroll
        for (int mt = 0; mt < 2; ++mt)
            #pragma unroll
            for (int hf = 0; hf < 2; ++hf) {
                int pt = m_block + wm*32 + mt*16 + hf*8 + r4;
                float v0 = c[mt][nt][2*hf] + bv.x;
                float v1 = c[mt][nt][2*hf+1] + bv.y;
                float l0, l1;
                uint32_t hp = packbf(v0, v1, l0, l1);
                uint32_t lp = packlo(l0, l1);
                *(uint32_t*)(oH + (size_t)pt*256 + col) = hp;
                *(uint32_t*)(oL + (size_t)pt*256 + col) = lp;
            }
    }
}

// ======== fused query-proj: gelu -> GEMM(qpW2) -> LN -> GEMM(Wq) -> g_Q ========
// smem: persistent A slab 8 chunks x 16KB (h@0, l@8192) = 131072
//       2 B-only stage slabs 32KB (h@0, l@16384)
//       LN scratch 4KB
#define QPX 131072u
#define QPSLAB 32768u
#define QP_SMEM (131072 + 2*32768 + 4096)

__global__ void __launch_bounds__(512, 1)
qproj_fused(const float* __restrict__ qpW1, const float* __restrict__ qpb1,
            const float* __restrict__ qp_b2,
            const float* __restrict__ lng, const float* __restrict__ lnb,
            const float* __restrict__ in_b, float scale,
            const float* __restrict__ coords) {
    extern __shared__ char smraw[];
    uint32_t sb = smem_u32(smraw);
    uint32_t stoff = sb + QPX;
    int tid = threadIdx.x, lane = tid & 31, w = tid >> 5;
    int wn = w & 3, wm = w >> 2;
    int m_block = blockIdx.x * 128;

    int sub = lane & 7, blk = lane >> 3;
    int rowoff = sub + ((blk & 1) << 3);
    uint32_t koffB = (uint32_t)((blk >> 1) << 4);
    uint32_t aoff[2][2], boff[4][2];
    #pragma unroll
    for (int mt = 0; mt < 2; ++mt)
        #pragma unroll
        for (int kh = 0; kh < 2; ++kh)
            aoff[mt][kh] = SW64((uint32_t)((wm*32 + mt*16 + rowoff)*64 + kh*32) + koffB);
    #pragma unroll
    for (int ng = 0; ng < 4; ++ng)
        #pragma unroll
        for (int kh = 0; kh < 2; ++kh)
            boff[ng][kh] = SW64((uint32_t)((wn*64 + ng*16 + rowoff)*64 + kh*32) + koffB);

    int r4 = lane >> 2, kp2 = (lane & 3)*2;

    // ---- compute gelu A once into persistent slab ----
    {
        int r = tid >> 2, seg = tid & 3;
        float2 xy = *(const float2*)(coords + 2*(m_block + r));
        float cxp = xy.x, cyp = xy.y;
        for (int cth = 0; cth < 8; ++cth) {
            uint32_t sA = sb + (uint32_t)cth*16384u + SW64((uint32_t)(r*64 + seg*16));
            #pragma unroll
            for (int j2 = 0; j2 < 4; ++j2) {
                int h = cth*32 + seg*8 + j2*2;
                float4 wv = *(const float4*)(qpW1 + 2*h);
                float2 bv = *(const float2*)(qpb1 + h);
                float u0 = wv.x*cxp + wv.y*cyp + bv.x;
                float u1 = wv.z*cxp + wv.w*cyp + bv.y;
                float v0 = 0.5f*u0*(1.f + erff(u0*0.70710678118654752f));
                float v1 = 0.5f*u1*(1.f + erff(u1*0.70710678118654752f));
                float l0, l1;
                uint32_t hp = packbf(v0, v1, l0, l1);
                uint32_t lp = packlo(l0, l1);
                asm volatile("st.shared.b32 [%0], %1;" :: "r"(sA + j2*4), "r"(hp) : "memory");
                asm volatile("st.shared.b32 [%0], %1;" :: "r"(sA + 8192u + j2*4), "r"(lp) : "memory");
            }
        }
    }

    auto prefetchB = [&](int mat, int cc, uint32_t stb) {
        const __nv_bfloat16* BHp = g_Bh + (size_t)mat*65536;
        const __nv_bfloat16* BLp = g_Bl + (size_t)mat*65536;
        int r = tid >> 2, seg = tid & 3;
        size_t go = (size_t)cc*32 + seg*8;
        #pragma unroll
        for (int it = 0; it < 2; ++it) {
            int row = r + it*128;
            uint32_t sB = stb + SW64((uint32_t)(row*64 + seg*16));
            CP16(sB, BHp + (size_t)row*256 + go);
            CP16(sB + 16384u, BLp + (size_t)row*256 + go);
        }
    };

    float c[2][8][4];
    int s = 0;
    prefetchB(0, 0, stoff);
    CP_COMMIT();

    for (int pass = 0; pass < 2; ++pass) {
        #pragma unroll
        for (int mt = 0; mt < 2; ++mt)
            #pragma unroll
            for (int nt = 0; nt < 8; ++nt)
                #pragma unroll
                for (int i = 0; i < 4; ++i) c[mt][nt][i] = 0.f;

        for (int i = 0; i < 8; ++i) {
            CP_WAIT0();
            __syncthreads();
            int gi = pass*8 + i;
            if (gi + 1 < 16) {
                prefetchB((gi+1) >> 3, (gi+1) & 7, stoff + (uint32_t)((s+1) & 1)*QPSLAB);
                CP_COMMIT();
            }
            uint32_t Abase = sb + (uint32_t)i*16384u;
            uint32_t Bbase = stoff + (uint32_t)(s & 1)*QPSLAB;
            #pragma unroll
            for (int kh = 0; kh < 2; ++kh) {
                uint32_t ah[2][4], al[2][4];
                ldsm4(ah[0], Abase + aoff[0][kh]);
                ldsm4(ah[1], Abase + aoff[1][kh]);
                ldsm4(al[0], Abase + 8192u + aoff[0][kh]);
                ldsm4(al[1], Abase + 8192u + aoff[1][kh]);
                #pragma unroll
                for (int ng = 0; ng < 4; ++ng) {
                    uint32_t bh[4], bl[4];
                    ldsm4(bh, Bbase + boff[ng][kh]);
                    ldsm4(bl, Bbase + 16384u + boff[ng][kh]);
                    #pragma unroll
                    for (int mt = 0; mt < 2; ++mt) {
                        mma16816(c[mt][2*ng],   ah[mt], bh[0], bh[2]);
                        mma16816(c[mt][2*ng+1], ah[mt], bh[1], bh[3]);
                        mma16816(c[mt][2*ng],   al[mt], bh[0], bh[2]);
                        mma16816(c[mt][2*ng+1], al[mt], bh[1], bh[3]);
                        mma16816(c[mt][2*ng],   ah[mt], bl[0], bl[2]);
                        mma16816(c[mt][2*ng+1], ah[mt], bl[1], bl[3]);
                    }
                }
            }
            ++s;
        }
        __syncthreads();   // all A reads done before slab overwrite / before Q epilogue

        if (pass == 0) {
            // ---- LN epilogue: bias qp_b2 + LayerNorm -> X1 into persistent slab ----
            float* sLN  = (float*)(smraw + QPX + 2*QPSLAB);   // dedicated 4KB scratch
            float* sLN2 = sLN + 512;
            #pragma unroll
            for (int nt = 0; nt < 8; ++nt) {
                float2 bv = *(const float2*)(qp_b2 + wn*64 + nt*8 + kp2);
                #pragma unroll
                for (int mt = 0; mt < 2; ++mt) {
                    c[mt][nt][0] += bv.x; c[mt][nt][1] += bv.y;
                    c[mt][nt][2] += bv.x; c[mt][nt][3] += bv.y;
                }
            }
            #pragma unroll
            for (int mt = 0; mt < 2; ++mt)
                #pragma unroll
                for (int hf = 0; hf < 2; ++hf) {
                    float sv = 0.f, ssv = 0.f;
                    #pragma unroll
                    for (int nt = 0; nt < 8; ++nt) {
                        float v0 = c[mt][nt][2*hf], v1 = c[mt][nt][2*hf+1];
                        sv += v0 + v1; ssv += v0*v0 + v1*v1;
                    }
                    sv  += __shfl_xor_sync(0xffffffffu, sv, 1);  sv += __shfl_xor_sync(0xffffffffu, sv, 2);
                    ssv += __shfl_xor_sync(0xffffffffu, ssv, 1); ssv += __shfl_xor_sync(0xffffffffu, ssv, 2);
                    if ((lane & 3) == 0) {
                        int rl = wm*32 + mt*16 + hf*8 + r4;
                        sLN[rl*4 + wn] = sv; sLN2[rl*4 + wn] = ssv;
                    }
                }
            __syncthreads();
            float muv[2][2], rsv[2][2];
            #pragma unroll
            for (int mt = 0; mt < 2; ++mt)
                #pragma unroll
                for (int hf = 0; hf < 2; ++hf) {
                    int rl = wm*32 + mt*16 + hf*8 + r4;
                    float S  = sLN[rl*4]  + sLN[rl*4+1]  + sLN[rl*4+2]  + sLN[rl*4+3];
                    float SS = sLN2[rl*4] + sLN2[rl*4+1] + sLN2[rl*4+2] + sLN2[rl*4+3];
                    float mu = S * (1.f/256.f);
                    muv[mt][hf] = mu;
                    rsv[mt][hf] = rsqrtf(SS * (1.f/256.f) - mu*mu + 1e-5f);
                }
            #pragma unroll
            for (int nt = 0; nt < 8; ++nt) {
                int col = wn*64 + nt*8 + kp2;
                float2 lg = *(const float2*)(lng + col);
                float2 lb = *(const float2*)(lnb + col);
                #pragma unroll
                for (int mt = 0; mt < 2; ++mt)
                    #pragma unroll
                    for (int hf = 0; hf < 2; ++hf) {
                        float v0 = (c[mt][nt][2*hf]   - muv[mt][hf]) * rsv[mt][hf] * lg.x + lb.x;
                        float v1 = (c[mt][nt][2*hf+1] - muv[mt][hf]) * rsv[mt][hf] * lg.y + lb.y;
                        float l0, l1;
                        uint32_t hp = packbf(v0, v1, l0, l1);
                        uint32_t lp = packlo(l0, l1);
                        int rl = wm*32 + mt*16 + hf*8 + r4;
                        uint32_t xo = sb + (uint32_t)(col >> 5)*16384u
                                    + SW64((uint32_t)(rl*64 + (col & 31)*2));
                        asm volatile("st.shared.b32 [%0], %1;" :: "r"(xo), "r"(hp) : "memory");
                        asm volatile("st.shared.b32 [%0], %1;" :: "r"(xo + 8192u), "r"(lp) : "memory");
                    }
            }
            // next pass's first CP_WAIT0+__syncthreads orders these writes before A reads
        } else {
            // ---- Q epilogue: + in_b, * scale -> g_Q fp32 ----
            #pragma unroll
            for (int nt = 0; nt < 8; ++nt) {
                int col = wn*64 + nt*8 + kp2;
                float2 bv = *(const float2*)(in_b + col);
                #pragma unroll
                for (int mt = 0; mt < 2; ++mt)
                    #pragma unroll
                    for (int hf = 0; hf < 2; ++hf) {
                        int pt = m_block + wm*32 + mt*16 + hf*8 + r4;
                        float v0 = (c[mt][nt][2*hf]   + bv.x) * scale;
                        float v1 = (c[mt][nt][2*hf+1] + bv.y) * scale;
                        *(float2*)(g_Q + (size_t)pt*256 + col) = make_float2(v0, v1);
                    }
            }
        }
    }
}

// ======== fused MFN kernel: L0..L4 + fragment-direct fin + irfft ========
#define FX_BYTES 131072u
#define FSLAB 49152u
#define FUSED_SMEM (131072 + 2*49152)

__global__ void __launch_bounds__(512, 1)
mfn_fused(const float* __restrict__ net1_b,
          const float* __restrict__ gW, const float* __restrict__ gb,
          const float* __restrict__ gmu, const float* __restrict__ gga,
          const float* __restrict__ coords,
          const float* __restrict__ fin_W, const float* __restrict__ fin_b,
          float* __restrict__ out) {
    extern __shared__ char smraw[];
    uint32_t sb = smem_u32(smraw);
    uint32_t stoff = sb + FX_BYTES;
    int tid = threadIdx.x, lane = tid & 31, w = tid >> 5;
    int wn = w & 3, wm = w >> 2;
    int m_block = blockIdx.x * 128;

    int sub = lane & 7, blk = lane >> 3;
    int rowoff = sub + ((blk & 1) << 3);
    uint32_t koffB = (uint32_t)((blk >> 1) << 4);
    uint32_t aoff[2][2], boff[4][2];
    #pragma unroll
    for (int mt = 0; mt < 2; ++mt)
        #pragma unroll
        for (int kh = 0; kh < 2; ++kh)
            aoff[mt][kh] = SW64((uint32_t)((wm*32 + mt*16 + rowoff)*64 + kh*32) + koffB);
    #pragma unroll
    for (int ng = 0; ng < 4; ++ng)
        #pragma unroll
        for (int kh = 0; kh < 2; ++kh)
            boff[ng][kh] = SW64((uint32_t)((wn*64 + ng*16 + rowoff)*64 + kh*32) + koffB);

    int r4 = lane >> 2, kp2 = (lane & 3)*2;
    float cx[2][2], cy[2][2], rr2[2][2];
    #pragma unroll
    for (int mt = 0; mt < 2; ++mt)
        #pragma unroll
        for (int hf = 0; hf < 2; ++hf) {
            int pt = m_block + wm*32 + mt*16 + hf*8 + r4;
            float2 xy = *(const float2*)(coords + 2*pt);
            cx[mt][hf] = xy.x; cy[mt][hf] = xy.y; rr2[mt][hf] = xy.x*xy.x + xy.y*xy.y;
        }

    auto prefetch = [&](int L, int i, uint32_t stb) {
        bool loadA; int ch, matB;
        if (L == 0)      { loadA = true;  ch = i;     matB = 3; }
        else if (i < 8)  { loadA = false; ch = i;     matB = 8 + (L-1); }
        else             { loadA = true;  ch = i - 8; matB = 3 + L; }
        const __nv_bfloat16* BHp = g_Bh + (size_t)matB*65536;
        const __nv_bfloat16* BLp = g_Bl + (size_t)matB*65536;
        int r = tid >> 2, seg = tid & 3;
        size_t go = (size_t)ch*32 + seg*8;
        if (loadA) {
            size_t aofs = (size_t)(m_block + r)*256 + go;
            uint32_t sA = stb + SW64((uint32_t)(r*64 + seg*16));
            CP16(sA, g_Z2h + aofs);
            CP16(sA + OFF_AL, g_Z2l + aofs);
        }
        #pragma unroll
        for (int it = 0; it < 2; ++it) {
            int row = r + it*128;
            uint32_t sB = stb + OFF_BH + SW64((uint32_t)(row*64 + seg*16));
            CP16(sB, BHp + (size_t)row*256 + go);
            CP16(sB + 16384u, BLp + (size_t)row*256 + go);
        }
    };

    float c[2][8][4];
    int s = 0;
    prefetch(0, 0, stoff);
    CP_COMMIT();

    for (int L = 0; L <= 4; ++L) {
        int np = (L == 0) ? 8 : 16;
        #pragma unroll
        for (int mt = 0; mt < 2; ++mt)
            #pragma unroll
            for (int nt = 0; nt < 8; ++nt)
                #pragma unroll
                for (int i = 0; i < 4; ++i) c[mt][nt][i] = 0.f;

        for (int i = 0; i < np; ++i) {
            CP_WAIT0();
            __syncthreads();
            {
                int nL = L, ni = i + 1;
                if (ni == np) { nL = L + 1; ni = 0; }
                if (nL <= 4) {
                    prefetch(nL, ni, stoff + (uint32_t)((s+1) & 1)*FSLAB);
                    CP_COMMIT();
                }
            }
            bool isx = (L > 0 && i < 8);
            uint32_t stb = stoff + (uint32_t)(s & 1)*FSLAB;
            uint32_t Abase = isx ? (sb + (uint32_t)i*16384u) : stb;
            uint32_t Bbase = stb;
            #pragma unroll
            for (int kh = 0; kh < 2; ++kh) {
                uint32_t ah[2][4], al[2][4];
                ldsm4(ah[0], Abase + aoff[0][kh]);
                ldsm4(ah[1], Abase + aoff[1][kh]);
                ldsm4(al[0], Abase + OFF_AL + aoff[0][kh]);
                ldsm4(al[1], Abase + OFF_AL + aoff[1][kh]);
                #pragma unroll
                for (int ng = 0; ng < 4; ++ng) {
                    uint32_t bh[4], bl[4];
                    ldsm4(bh, Bbase + OFF_BH + boff[ng][kh]);
                    ldsm4(bl, Bbase + OFF_BL + boff[ng][kh]);
                    #pragma unroll
                    for (int mt = 0; mt < 2; ++mt) {
                        mma16816(c[mt][2*ng],   ah[mt], bh[0], bh[2]);
                        mma16816(c[mt][2*ng+1], ah[mt], bh[1], bh[3]);
                        mma16816(c[mt][2*ng],   al[mt], bh[0], bh[2]);
                        mma16816(c[mt][2*ng+1], al[mt], bh[1], bh[3]);
                        mma16816(c[mt][2*ng],   ah[mt], bl[0], bl[2]);
                        mma16816(c[mt][2*ng+1], ah[mt], bl[1], bl[3]);
                    }
                }
            }
            ++s;
        }
        __syncthreads();

        // ---- epilogue layer L ----
        #pragma unroll
        for (int nt = 0; nt < 8; ++nt) {
            int col = wn*64 + nt*8 + kp2;
            if (L > 0) {
                float2 bv = *(const float2*)(net1_b + (L-1)*256 + col);
                #pragma unroll
                for (int mt = 0; mt < 2; ++mt) {
                    c[mt][nt][0] += bv.x; c[mt][nt][1] += bv.y;
                    c[mt][nt][2] += bv.x; c[mt][nt][3] += bv.y;
                }
            }
            int idx = L*256 + col;
            float4 wv = *(const float4*)(gW + 2*idx);
            float4 mv = *(const float4*)(gmu + 2*idx);
            float2 bb = *(const float2*)(gb + idx);
            float2 gv = *(const float2*)(gga + idx);
            float mu20 = mv.x*mv.x + mv.y*mv.y;
            float mu21 = mv.z*mv.z + mv.w*mv.w;
            #pragma unroll
            for (int mt = 0; mt < 2; ++mt)
                #pragma unroll
                for (int hf = 0; hf < 2; ++hf) {
                    float x = cx[mt][hf], y = cy[mt][hf], r2 = rr2[mt][hf];
                    float D0 = r2 + mu20 - 2.f*(x*mv.x + y*mv.y);
                    float D1 = r2 + mu21 - 2.f*(x*mv.z + y*mv.w);
                    float v0 = c[mt][nt][2*hf]   * (sinf(wv.x*x + wv.y*y + bb.x) * __expf(-0.5f*D0*gv.x));
                    float v1 = c[mt][nt][2*hf+1] * (sinf(wv.z*x + wv.w*y + bb.y) * __expf(-0.5f*D1*gv.y));
                    if (L < 4) {
                        float l0, l1;
                        uint32_t hp = packbf(v0, v1, l0, l1);
                        uint32_t lp = packlo(l0, l1);
                        int rl = wm*32 + mt*16 + hf*8 + r4;
                        uint32_t xo = sb + (uint32_t)(col >> 5)*16384u
                                    + SW64((uint32_t)(rl*64 + (col & 31)*2));
                        asm volatile("st.shared.b32 [%0], %1;" :: "r"(xo), "r"(hp) : "memory");
                        asm volatile("st.shared.b32 [%0], %1;" :: "r"(xo + OFF_AL), "r"(lp) : "memory");
                    } else {
                        c[mt][nt][2*hf]   = v0;
                        c[mt][nt][2*hf+1] = v1;
                    }
                }
        }
    }
    __syncthreads();

    // ======== fragment-direct fin + irfft ========
    {
        float* sW   = (float*)smraw;           // [128][36][4]
        float* sF   = sW + 128*36*4;           // [128][36]
        float* sTab = sF + 128*36;             // [32]
        if (tid < 16) {
            float sv, cv;
            sincosf(0.39269908169872414f * (float)tid, &sv, &cv);
            sTab[2*tid] = cv; sTab[2*tid+1] = sv;
        }
        for (int g = 0; g < 36; ++g) {
            ull acc0 = 0ull, acc1 = 0ull, acc2 = 0ull, acc3 = 0ull;
            const float* Wg = fin_W + g*256 + wn*64 + kp2;
            #pragma unroll
            for (int nt = 0; nt < 8; ++nt) {
                float2 wvv = *(const float2*)(Wg + nt*8);
                ull wp = pack2(wvv.x, wvv.y);
                fma2(acc0, pack2(c[0][nt][0], c[0][nt][1]), wp);
                fma2(acc1, pack2(c[0][nt][2], c[0][nt][3]), wp);
                fma2(acc2, pack2(c[1][nt][0], c[1][nt][1]), wp);
                fma2(acc3, pack2(c[1][nt][2], c[1][nt][3]), wp);
            }
            float f0 = fold2(acc0), f1 = fold2(acc1), f2 = fold2(acc2), f3 = fold2(acc3);
            f0 += __shfl_xor_sync(0xffffffffu, f0, 1); f0 += __shfl_xor_sync(0xffffffffu, f0, 2);
            f1 += __shfl_xor_sync(0xffffffffu, f1, 1); f1 += __shfl_xor_sync(0xffffffffu, f1, 2);
            f2 += __shfl_xor_sync(0xffffffffu, f2, 1); f2 += __shfl_xor_sync(0xffffffffu, f2, 2);
            f3 += __shfl_xor_sync(0xffffffffu, f3, 1); f3 += __shfl_xor_sync(0xffffffffu, f3, 2);
            if ((lane & 3) == 0) {
                int rbase = wm*32 + r4;
                sW[(rbase     )*144 + g*4 + wn] = f0;
                sW[(rbase +  8)*144 + g*4 + wn] = f1;
                sW[(rbase + 16)*144 + g*4 + wn] = f2;
                sW[(rbase + 24)*144 + g*4 + wn] = f3;
            }
        }
        __syncthreads();
        if (tid < 128) {
            const float* wp = sW + tid*144;
            #pragma unroll 4
            for (int g = 0; g < 36; ++g)
                sF[tid*36 + g] = wp[g*4] + wp[g*4+1] + wp[g*4+2] + wp[g*4+3] + fin_b[g];
        }
        __syncthreads();
        int pc = tid & 255;
        int pp2 = pc >> 1, ch = pc & 1;
        int tg = tid >> 8;
        const float* Fp = &sF[pp2*36];
        int b = m_block >> 14;
        int n0p = (m_block & (NPTS-1)) + pp2;
        #pragma unroll
        for (int it = 0; it < 8; ++it) {
            int tt = tg + 2*it;
            float a = Fp[ch*2];
            float f8 = Fp[8*4 + ch*2];
            a += (tt & 1) ? -f8 : f8;
            #pragma unroll
            for (int fq = 1; fq < 8; ++fq) {
                float re = Fp[fq*4 + ch*2], im = Fp[fq*4 + ch*2 + 1];
                int k = (fq*tt) & 15;
                a += 2.f * (re*sTab[2*k] - im*sTab[2*k+1]);
            }
            out[(((b*16 + tt)*NPTS) + n0p)*2 + ch] = 0.25f * a;
        }
    }
}

// ======== attention (scalar) ========
#define ATTN_SMF (5120 + P*512)
__global__ void __launch_bounds__(256, 2) attn_kernel() {
    extern __shared__ float smf[];
    float* sA = smf;
    float* sS = sA + 5120;
    int t = threadIdx.x, lane = t & 31, w = t >> 5;
    int bid = blockIdx.x, b = bid >> 10, n0 = (bid & 1023) * P;
    size_t base = (size_t)(b*NPTS + n0) * 256;
    #pragma unroll
    for (int p = 0; p < P; ++p) sA[t*PP + p] = g_Q[base + (size_t)p*256 + t];
    __syncthreads();
    #pragma unroll
    for (int rep = 0; rep < 2; ++rep) {
        int pair = t + rep*256, hh = pair >> 6, m = pair & 63;
        const float* Kp = &g_Kt[((b*8 + hh)*32)*M_KV + m];
        ull a2[8];
        #pragma unroll
        for (int j = 0; j < 8; ++j) a2[j] = 0ull;
        #pragma unroll 4
        for (int k = 0; k < 32; ++k) {
            float kv = Kp[k*M_KV];
            ull kk = pack2(kv, kv);
            const ulonglong2* col = (const ulonglong2*)(sA + (hh*32 + k)*PP);
            #pragma unroll
            for (int q = 0; q < 4; ++q) { ulonglong2 x = col[q]; fma2(a2[2*q], x.x, kk); fma2(a2[2*q+1], x.y, kk); }
        }
        #pragma unroll
        for (int j = 0; j < 8; ++j) {
            float lo, hi; unpack2(a2[j], lo, hi);
            sS[(2*j)*512 + pair] = lo; sS[(2*j+1)*512 + pair] = hi;
        }
    }
    __syncthreads();
    for (int rr = 0; rr < 16; ++rr) {
        int r = w + rr*8, p = r >> 3, hh = r & 7;
        float* bs = &sS[p*512 + hh*64];
        float v0 = bs[lane], v1 = bs[lane+32];
        float mx = fmaxf(v0, v1);
        #pragma unroll
        for (int o = 16; o; o >>= 1) mx = fmaxf(mx, __shfl_xor_sync(0xffffffffu, mx, o));
        float e0 = __expf(v0-mx), e1 = __expf(v1-mx), sum = e0 + e1;
        #pragma unroll
        for (int o = 16; o; o >>= 1) sum += __shfl_xor_sync(0xffffffffu, sum, o);
        float inv = 1.f/sum;
        bs[lane] = e0*inv; bs[lane+32] = e1*inv;
    }
    __syncthreads();
    {
        int hh = t >> 5;
        ull acc[P];
        #pragma unroll
        for (int p = 0; p < P; ++p) acc[p] = 0ull;
        const float* Vb = g_Vt + b*32*512;
        #pragma unroll 2
        for (int m = 0; m < M_KV; m += 2) {
            ull vv = *(const ull*)(Vb + ((m>>1)*256 + t)*2);
            #pragma unroll
            for (int p = 0; p < P; ++p) fma2(acc[p], *(const ull*)(&sS[p*512 + hh*64 + m]), vv);
        }
        #pragma unroll
        for (int p = 0; p < P; ++p) {
            float v = fold2(acc[p]);
            __nv_bfloat16 h = __float2bfloat16_rn(v);
            g_X0h[base + (size_t)p*256 + t] = h;
            g_X0l[base + (size_t)p*256 + t] = __float2bfloat16_rn(v - __bfloat162float(h));
        }
    }
}

// ======== launch ========
extern "C" void kernel_launch(void* const* d_in, const int* in_sizes, int n_in,
                              void* d_out, int out_size) {
    const float* z_multi=(const float*)d_in[0];  const float* coords=(const float*)d_in[1];
    const float* gabor_W=(const float*)d_in[2];  const float* gabor_b=(const float*)d_in[3];
    const float* gabor_mu=(const float*)d_in[4]; const float* gabor_ga=(const float*)d_in[5];
    const float* net1_W=(const float*)d_in[6];   const float* net1_b=(const float*)d_in[7];
    const float* net2_W=(const float*)d_in[8];   const float* qp_W1=(const float*)d_in[9];
    const float* qp_b1=(const float*)d_in[10];   const float* qp_W2=(const float*)d_in[11];
    const float* qp_b2=(const float*)d_in[12];   const float* in_W=(const float*)d_in[13];
    const float* in_b=(const float*)d_in[14];    const float* out_W=(const float*)d_in[15];
    const float* out_b=(const float*)d_in[16];   const float* lnq_g=(const float*)d_in[17];
    const float* lnq_b=(const float*)d_in[18];   const float* lnkv_g=(const float*)d_in[19];
    const float* lnkv_b=(const float*)d_in[20];  const float* fin_W=(const float*)d_in[21];
    const float* fin_b=(const float*)d_in[22];
    float* out = (float*)d_out;

    cudaFuncSetAttribute(gemm_bias,   cudaFuncAttributeMaxDynamicSharedMemorySize, GEMM_SMEM);
    cudaFuncSetAttribute(qproj_fused, cudaFuncAttributeMaxDynamicSharedMemorySize, QP_SMEM);
    cudaFuncSetAttribute(mfn_fused,   cudaFuncAttributeMaxDynamicSharedMemorySize, FUSED_SMEM);
    cudaFuncSetAttribute(attn_kernel, cudaFuncAttributeMaxDynamicSharedMemorySize, ATTN_SMF*4);

    conv_w<<<dim3(256,14), 256>>>(qp_W2, in_W, out_W, net2_W, net1_W);
    kv_kernel<<<BATCH*M_KV/8, 256>>>(z_multi, lnkv_g, lnkv_b, in_b);

    int G = TOTM/128;
    const float qscale = 0.17677669529663687f;  // 1/sqrt(32)
    // Q = ((LN(gelu(x0@qpW1+b1) @ qpW2^T + b2)) @ Wq^T + bq)*scale -> g_Q (one kernel)
    qproj_fused<<<G,512,QP_SMEM>>>(qp_W1, qp_b1, qp_b2, lnq_g, lnq_b, in_b, qscale, coords);
    attn_kernel<<<BATCH*(NPTS/P), 256, ATTN_SMF*4>>>();
    // z = ctx @ outW^T + out_b -> Z2
    gemm_bias<<<G,512,GEMM_SMEM>>>(0, 2, 1, out_b);
    // fused MFN L0..L4 + fin + irfft -> out
    mfn_fused<<<G,512,FUSED_SMEM>>>(net1_b, gabor_W, gabor_b, gabor_mu, gabor_ga, coords,
                                    fin_W, fin_b, out);
}

// round 17
// speedup vs baseline: 1.1989x; 1.0196x over previous
#include <cuda_runtime.h>
#include <cuda_bf16.h>
#include <math.h>
#include <stdint.h>

#define BATCH 8
#define NPTS  16384
#define M_KV  64
#define TOTM  (BATCH*NPTS)
#define P     16
#define PP    20
typedef unsigned long long ull;

// ======== PTX helpers ========
__device__ __forceinline__ uint32_t smem_u32(const void* p) {
    uint32_t a;
    asm("{ .reg .u64 t; cvta.to.shared.u64 t, %1; cvt.u32.u64 %0, t; }" : "=r"(a) : "l"(p));
    return a;
}
#define CP16(dst, src) asm volatile("cp.async.cg.shared.global [%0], [%1], 16;" :: "r"(dst), "l"(src) : "memory")
#define CP_COMMIT()    asm volatile("cp.async.commit_group;" ::: "memory")
#define CP_WAIT0()     asm volatile("cp.async.wait_group 0;" ::: "memory")
__device__ __forceinline__ void ldsm4(uint32_t* r, uint32_t addr) {
    asm volatile("ldmatrix.sync.aligned.m8n8.x4.shared.b16 {%0,%1,%2,%3}, [%4];"
        : "=r"(r[0]), "=r"(r[1]), "=r"(r[2]), "=r"(r[3]) : "r"(addr));
}
__device__ __forceinline__ void mma16816(float* c, const uint32_t* a, uint32_t b0, uint32_t b1) {
    asm volatile("mma.sync.aligned.m16n8k16.row.col.f32.bf16.bf16.f32 "
        "{%0,%1,%2,%3}, {%4,%5,%6,%7}, {%8,%9}, {%0,%1,%2,%3};"
        : "+f"(c[0]), "+f"(c[1]), "+f"(c[2]), "+f"(c[3])
        : "r"(a[0]), "r"(a[1]), "r"(a[2]), "r"(a[3]), "r"(b0), "r"(b1));
}
#define SW64(o) ((o) ^ (((o) >> 3) & 0x30))
__device__ __forceinline__ void fma2(ull& a, ull x, ull w) {
    asm("fma.rn.f32x2 %0, %1, %2, %0;" : "+l"(a) : "l"(x), "l"(w));
}
__device__ __forceinline__ float fold2(ull v) { float lo,hi; asm("mov.b64 {%0,%1}, %2;" : "=f"(lo),"=f"(hi) : "l"(v)); return lo+hi; }
__device__ __forceinline__ void unpack2(ull v, float& lo, float& hi) { asm("mov.b64 {%0,%1}, %2;" : "=f"(lo),"=f"(hi) : "l"(v)); }
__device__ __forceinline__ ull pack2(float lo, float hi) { ull r; asm("mov.b64 %0, {%1,%2};" : "=l"(r) : "f"(lo),"f"(hi)); return r; }
__device__ __forceinline__ uint32_t packbf(float v0, float v1, float& r0, float& r1) {
    __nv_bfloat16 h0 = __float2bfloat16_rn(v0);
    __nv_bfloat16 h1 = __float2bfloat16_rn(v1);
    r0 = v0 - __bfloat162float(h0);
    r1 = v1 - __bfloat162float(h1);
    unsigned short a = *(unsigned short*)&h0, b = *(unsigned short*)&h1;
    return (uint32_t)a | ((uint32_t)b << 16);
}
__device__ __forceinline__ uint32_t packlo(float l0, float l1) {
    __nv_bfloat16 a = __float2bfloat16_rn(l0);
    __nv_bfloat16 b = __float2bfloat16_rn(l1);
    unsigned short x = *(unsigned short*)&a, y = *(unsigned short*)&b;
    return (uint32_t)x | ((uint32_t)y << 16);
}

// ======== global scratch ========
#define SZ ((size_t)TOTM * 256)
__device__ __nv_bfloat16 g_X0h[SZ], g_X0l[SZ], g_Z2h[SZ], g_Z2l[SZ];
__device__ float g_Q[SZ];
__device__ __nv_bfloat16 g_Bh[12*65536], g_Bl[12*65536];
__device__ float g_WkT[65536], g_WvT[65536];
__device__ float g_Kt[BATCH*8*32*M_KV];
__device__ float g_Vt[BATCH*32*256*2];
__device__ __forceinline__ __nv_bfloat16* selH(int s){ return s==0?g_X0h:g_Z2h; }
__device__ __forceinline__ __nv_bfloat16* selL(int s){ return s==0?g_X0l:g_Z2l; }

// ======== prep kernels ========
__global__ void conv_w(const float* __restrict__ qp_W2, const float* __restrict__ in_W,
                       const float* __restrict__ out_W, const float* __restrict__ net2_W,
                       const float* __restrict__ net1_W) {
    int n = blockIdx.x, mat = blockIdx.y, k = threadIdx.x;
    if (mat >= 12) {
        const float* src = in_W + (size_t)(mat == 12 ? 256 : 512) * 256;
        float* dst = (mat == 12) ? g_WkT : g_WvT;
        dst[k*256 + n] = src[n*256 + k];
        return;
    }
    const float* src;
    switch (mat) {
        case 0: src = qp_W2; break;
        case 1: src = in_W;  break;
        case 2: src = out_W; break;
        default: src = (mat < 8) ? net2_W + (mat-3)*65536 : net1_W + (mat-8)*65536;
    }
    float w = src[n*256 + k];
    __nv_bfloat16 h = __float2bfloat16_rn(w);
    g_Bh[mat*65536 + n*256 + k] = h;
    g_Bl[mat*65536 + n*256 + k] = __float2bfloat16_rn(w - __bfloat162float(h));
}

__global__ void kv_kernel(const float* __restrict__ z_multi,
                          const float* __restrict__ lnkv_g, const float* __restrict__ lnkv_b,
                          const float* __restrict__ in_b) {
    __shared__ float kvn[8][256];
    int t = threadIdx.x, lane = t & 31, w = t >> 5;
    int row0 = blockIdx.x * 8;
    {
        int row = row0 + w;
        float v[8];
        float s = 0.f, ss = 0.f;
        #pragma unroll
        for (int j = 0; j < 8; ++j) {
            v[j] = z_multi[(size_t)row*256 + lane*8 + j];
            s += v[j]; ss += v[j]*v[j];
        }
        #pragma unroll
        for (int o = 16; o; o >>= 1) {
            s  += __shfl_xor_sync(0xffffffffu, s,  o);
            ss += __shfl_xor_sync(0xffffffffu, ss, o);
        }
        float mu = s * (1.f/256.f);
        float rstd = rsqrtf(ss * (1.f/256.f) - mu*mu + 1e-5f);
        #pragma unroll
        for (int j = 0; j < 8; ++j) {
            int d = lane*8 + j;
            kvn[w][d] = (v[j] - mu) * rstd * lnkv_g[d] + lnkv_b[d];
        }
    }
    __syncthreads();
    float aK[8], aV[8];
    float bK = in_b[256+t], bV = in_b[512+t];
    #pragma unroll
    for (int i = 0; i < 8; ++i) { aK[i] = bK; aV[i] = bV; }
    #pragma unroll 4
    for (int d = 0; d < 256; ++d) {
        float wk = g_WkT[d*256 + t];
        float wv = g_WvT[d*256 + t];
        #pragma unroll
        for (int i = 0; i < 8; ++i) {
            float x = kvn[i][d];
            aK[i] += x * wk;
            aV[i] += x * wv;
        }
    }
    #pragma unroll
    for (int i = 0; i < 8; ++i) {
        int row = row0 + i, b = row >> 6, m = row & 63;
        g_Kt[((b*8 + (t>>5))*32 + (t&31))*M_KV + m] = aK[i];
        g_Vt[((b*32 + (m>>1))*256 + t)*2 + (m&1)] = aV[i];
    }
}

// ======== common offsets ========
#define OFF_AL 8192u
#define OFF_BH 16384u
#define OFF_BL 32768u
#define SLAB_BYTES 49152u
#define STAGE_BYTES 98304u
#define GEMM_SMEM (2*98304)

// ======== standalone GEMM (BIAS: z = ctx @ outW^T + out_b) ========
__device__ __forceinline__ void load_chunk_g(uint32_t base,
        const __nv_bfloat16* AH, const __nv_bfloat16* AL,
        const __nv_bfloat16* BH, const __nv_bfloat16* BL,
        int m0, int c, int tid) {
    int r = tid >> 2, seg = tid & 3;
    size_t aofs = (size_t)(m0 + r)*256 + c*32 + seg*8;
    uint32_t sA = base + SW64((uint32_t)(r*64 + seg*16));
    CP16(sA, AH + aofs);
    CP16(sA + OFF_AL, AL + aofs);
    #pragma unroll
    for (int it = 0; it < 2; ++it) {
        int row = r + it*128;
        size_t bofs = (size_t)row*256 + c*32 + seg*8;
        uint32_t sB = base + OFF_BH + SW64((uint32_t)(row*64 + seg*16));
        CP16(sB, BH + bofs);
        CP16(sB + 16384u, BL + bofs);
    }
}

__global__ void __launch_bounds__(512, 1)
gemm_bias(int srcA1, int matB1, int dst, const float* __restrict__ bias) {
    extern __shared__ char smraw[];
    uint32_t sb = smem_u32(smraw);
    int tid = threadIdx.x, lane = tid & 31, w = tid >> 5;
    int wn = w & 3, wm = w >> 2;
    int m_block = blockIdx.x * 128;

    const __nv_bfloat16* AH = selH(srcA1);
    const __nv_bfloat16* AL = selL(srcA1);
    const __nv_bfloat16* BH = g_Bh + (size_t)matB1*65536;
    const __nv_bfloat16* BL = g_Bl + (size_t)matB1*65536;

    int sub = lane & 7, blk = lane >> 3;
    int rowoff = sub + ((blk & 1) << 3);
    uint32_t koffB = (uint32_t)((blk >> 1) << 4);
    uint32_t aoff[2][2], boff[4][2];
    #pragma unroll
    for (int mt = 0; mt < 2; ++mt)
        #pragma unroll
        for (int kh = 0; kh < 2; ++kh)
            aoff[mt][kh] = SW64((uint32_t)((wm*32 + mt*16 + rowoff)*64 + kh*32) + koffB);
    #pragma unroll
    for (int ng = 0; ng < 4; ++ng)
        #pragma unroll
        for (int kh = 0; kh < 2; ++kh)
            boff[ng][kh] = SW64((uint32_t)((wn*64 + ng*16 + rowoff)*64 + kh*32) + koffB);

    float c[2][8][4];
    #pragma unroll
    for (int mt = 0; mt < 2; ++mt)
        #pragma unroll
        for (int nt = 0; nt < 8; ++nt)
            #pragma unroll
            for (int i = 0; i < 4; ++i) c[mt][nt][i] = 0.f;

    load_chunk_g(sb, AH, AL, BH, BL, m_block, 0, tid);
    load_chunk_g(sb + SLAB_BYTES, AH, AL, BH, BL, m_block, 1, tid);
    CP_COMMIT();

    for (int st = 0; st < 4; ++st) {
        CP_WAIT0();
        __syncthreads();
        if (st + 1 < 4) {
            int g = 2*(st+1);
            uint32_t nb = sb + ((st+1) & 1)*STAGE_BYTES;
            load_chunk_g(nb, AH, AL, BH, BL, m_block, g, tid);
            load_chunk_g(nb + SLAB_BYTES, AH, AL, BH, BL, m_block, g+1, tid);
            CP_COMMIT();
        }
        uint32_t stbase = sb + (st & 1)*STAGE_BYTES;
        #pragma unroll
        for (int sl = 0; sl < 2; ++sl) {
            uint32_t base = stbase + sl*SLAB_BYTES;
            #pragma unroll
            for (int kh = 0; kh < 2; ++kh) {
                uint32_t ah[2][4], al[2][4];
                ldsm4(ah[0], base + aoff[0][kh]);
                ldsm4(ah[1], base + aoff[1][kh]);
                ldsm4(al[0], base + OFF_AL + aoff[0][kh]);
                ldsm4(al[1], base + OFF_AL + aoff[1][kh]);
                #pragma unroll
                for (int ng = 0; ng < 4; ++ng) {
                    uint32_t bh[4], bl[4];
                    ldsm4(bh, base + OFF_BH + boff[ng][kh]);
                    ldsm4(bl, base + OFF_BL + boff[ng][kh]);
                    #pragma unroll
                    for (int mt = 0; mt < 2; ++mt) {
                        mma16816(c[mt][2*ng],   ah[mt], bh[0], bh[2]);
                        mma16816(c[mt][2*ng+1], ah[mt], bh[1], bh[3]);
                        mma16816(c[mt][2*ng],   al[mt], bh[0], bh[2]);
                        mma16816(c[mt][2*ng+1], al[mt], bh[1], bh[3]);
                        mma16816(c[mt][2*ng],   ah[mt], bl[0], bl[2]);
                        mma16816(c[mt][2*ng+1], ah[mt], bl[1], bl[3]);
                    }
                }
            }
        }
    }
    __syncthreads();

    int r4 = lane >> 2, kp2 = (lane & 3)*2;
    __nv_bfloat16* oH = selH(dst);
    __nv_bfloat16* oL = selL(dst);
    #pragma unroll
    for (int nt = 0; nt < 8; ++nt) {
        int col = wn*64 + nt*8 + kp2;
        float2 bv = *(const float2*)(bias + col);
        #pragma unroll
        for (int mt = 0; mt < 2; ++mt)
            #pragma unroll
            for (int hf = 0; hf < 2; ++hf) {
                int pt = m_block + wm*32 + mt*16 + hf*8 + r4;
                float v0 = c[mt][nt][2*hf] + bv.x;
                float v1 = c[mt][nt][2*hf+1] + bv.y;
                float l0, l1;
                uint32_t hp = packbf(v0, v1, l0, l1);
                uint32_t lp = packlo(l0, l1);
                *(uint32_t*)(oH + (size_t)pt*256 + col) = hp;
                *(uint32_t*)(oL + (size_t)pt*256 + col) = lp;
            }
    }
}

// ======== fused query-proj ========
#define QPX 131072u
#define QPSLAB 32768u
#define QP_SMEM (131072 + 2*32768 + 4096)

__global__ void __launch_bounds__(512, 1)
qproj_fused(const float* __restrict__ qpW1, const float* __restrict__ qpb1,
            const float* __restrict__ qp_b2,
            const float* __restrict__ lng, const float* __restrict__ lnb,
            const float* __restrict__ in_b, float scale,
            const float* __restrict__ coords) {
    extern __shared__ char smraw[];
    uint32_t sb = smem_u32(smraw);
    uint32_t stoff = sb + QPX;
    int tid = threadIdx.x, lane = tid & 31, w = tid >> 5;
    int wn = w & 3, wm = w >> 2;
    int m_block = blockIdx.x * 128;

    int sub = lane & 7, blk = lane >> 3;
    int rowoff = sub + ((blk & 1) << 3);
    uint32_t koffB = (uint32_t)((blk >> 1) << 4);
    uint32_t aoff[2][2], boff[4][2];
    #pragma unroll
    for (int mt = 0; mt < 2; ++mt)
        #pragma unroll
        for (int kh = 0; kh < 2; ++kh)
            aoff[mt][kh] = SW64((uint32_t)((wm*32 + mt*16 + rowoff)*64 + kh*32) + koffB);
    #pragma unroll
    for (int ng = 0; ng < 4; ++ng)
        #pragma unroll
        for (int kh = 0; kh < 2; ++kh)
            boff[ng][kh] = SW64((uint32_t)((wn*64 + ng*16 + rowoff)*64 + kh*32) + koffB);

    int r4 = lane >> 2, kp2 = (lane & 3)*2;

    {
        int r = tid >> 2, seg = tid & 3;
        float2 xy = *(const float2*)(coords + 2*(m_block + r));
        float cxp = xy.x, cyp = xy.y;
        for (int cth = 0; cth < 8; ++cth) {
            uint32_t sA = sb + (uint32_t)cth*16384u + SW64((uint32_t)(r*64 + seg*16));
            #pragma unroll
            for (int j2 = 0; j2 < 4; ++j2) {
                int h = cth*32 + seg*8 + j2*2;
                float4 wv = *(const float4*)(qpW1 + 2*h);
                float2 bv = *(const float2*)(qpb1 + h);
                float u0 = wv.x*cxp + wv.y*cyp + bv.x;
                float u1 = wv.z*cxp + wv.w*cyp + bv.y;
                float v0 = 0.5f*u0*(1.f + erff(u0*0.70710678118654752f));
                float v1 = 0.5f*u1*(1.f + erff(u1*0.70710678118654752f));
                float l0, l1;
                uint32_t hp = packbf(v0, v1, l0, l1);
                uint32_t lp = packlo(l0, l1);
                asm volatile("st.shared.b32 [%0], %1;" :: "r"(sA + j2*4), "r"(hp) : "memory");
                asm volatile("st.shared.b32 [%0], %1;" :: "r"(sA + 8192u + j2*4), "r"(lp) : "memory");
            }
        }
    }

    auto prefetchB = [&](int mat, int cc, uint32_t stb) {
        const __nv_bfloat16* BHp = g_Bh + (size_t)mat*65536;
        const __nv_bfloat16* BLp = g_Bl + (size_t)mat*65536;
        int r = tid >> 2, seg = tid & 3;
        size_t go = (size_t)cc*32 + seg*8;
        #pragma unroll
        for (int it = 0; it < 2; ++it) {
            int row = r + it*128;
            uint32_t sB = stb + SW64((uint32_t)(row*64 + seg*16));
            CP16(sB, BHp + (size_t)row*256 + go);
            CP16(sB + 16384u, BLp + (size_t)row*256 + go);
        }
    };

    float c[2][8][4];
    int s = 0;
    prefetchB(0, 0, stoff);
    CP_COMMIT();

    for (int pass = 0; pass < 2; ++pass) {
        #pragma unroll
        for (int mt = 0; mt < 2; ++mt)
            #pragma unroll
            for (int nt = 0; nt < 8; ++nt)
                #pragma unroll
                for (int i = 0; i < 4; ++i) c[mt][nt][i] = 0.f;

        for (int i = 0; i < 8; ++i) {
            CP_WAIT0();
            __syncthreads();
            int gi = pass*8 + i;
            if (gi + 1 < 16) {
                prefetchB((gi+1) >> 3, (gi+1) & 7, stoff + (uint32_t)((s+1) & 1)*QPSLAB);
                CP_COMMIT();
            }
            uint32_t Abase = sb + (uint32_t)i*16384u;
            uint32_t Bbase = stoff + (uint32_t)(s & 1)*QPSLAB;
            #pragma unroll
            for (int kh = 0; kh < 2; ++kh) {
                uint32_t ah[2][4], al[2][4];
                ldsm4(ah[0], Abase + aoff[0][kh]);
                ldsm4(ah[1], Abase + aoff[1][kh]);
                ldsm4(al[0], Abase + 8192u + aoff[0][kh]);
                ldsm4(al[1], Abase + 8192u + aoff[1][kh]);
                #pragma unroll
                for (int ng = 0; ng < 4; ++ng) {
                    uint32_t bh[4], bl[4];
                    ldsm4(bh, Bbase + boff[ng][kh]);
                    ldsm4(bl, Bbase + 16384u + boff[ng][kh]);
                    #pragma unroll
                    for (int mt = 0; mt < 2; ++mt) {
                        mma16816(c[mt][2*ng],   ah[mt], bh[0], bh[2]);
                        mma16816(c[mt][2*ng+1], ah[mt], bh[1], bh[3]);
                        mma16816(c[mt][2*ng],   al[mt], bh[0], bh[2]);
                        mma16816(c[mt][2*ng+1], al[mt], bh[1], bh[3]);
                        mma16816(c[mt][2*ng],   ah[mt], bl[0], bl[2]);
                        mma16816(c[mt][2*ng+1], ah[mt], bl[1], bl[3]);
                    }
                }
            }
            ++s;
        }
        __syncthreads();

        if (pass == 0) {
            float* sLN  = (float*)(smraw + QPX + 2*QPSLAB);
            float* sLN2 = sLN + 512;
            #pragma unroll
            for (int nt = 0; nt < 8; ++nt) {
                float2 bv = *(const float2*)(qp_b2 + wn*64 + nt*8 + kp2);
                #pragma unroll
                for (int mt = 0; mt < 2; ++mt) {
                    c[mt][nt][0] += bv.x; c[mt][nt][1] += bv.y;
                    c[mt][nt][2] += bv.x; c[mt][nt][3] += bv.y;
                }
            }
            #pragma unroll
            for (int mt = 0; mt < 2; ++mt)
                #pragma unroll
                for (int hf = 0; hf < 2; ++hf) {
                    float sv = 0.f, ssv = 0.f;
                    #pragma unroll
                    for (int nt = 0; nt < 8; ++nt) {
                        float v0 = c[mt][nt][2*hf], v1 = c[mt][nt][2*hf+1];
                        sv += v0 + v1; ssv += v0*v0 + v1*v1;
                    }
                    sv  += __shfl_xor_sync(0xffffffffu, sv, 1);  sv += __shfl_xor_sync(0xffffffffu, sv, 2);
                    ssv += __shfl_xor_sync(0xffffffffu, ssv, 1); ssv += __shfl_xor_sync(0xffffffffu, ssv, 2);
                    if ((lane & 3) == 0) {
                        int rl = wm*32 + mt*16 + hf*8 + r4;
                        sLN[rl*4 + wn] = sv; sLN2[rl*4 + wn] = ssv;
                    }
                }
            __syncthreads();
            float muv[2][2], rsv[2][2];
            #pragma unroll
            for (int mt = 0; mt < 2; ++mt)
                #pragma unroll
                for (int hf = 0; hf < 2; ++hf) {
                    int rl = wm*32 + mt*16 + hf*8 + r4;
                    float S  = sLN[rl*4]  + sLN[rl*4+1]  + sLN[rl*4+2]  + sLN[rl*4+3];
                    float SS = sLN2[rl*4] + sLN2[rl*4+1] + sLN2[rl*4+2] + sLN2[rl*4+3];
                    float mu = S * (1.f/256.f);
                    muv[mt][hf] = mu;
                    rsv[mt][hf] = rsqrtf(SS * (1.f/256.f) - mu*mu + 1e-5f);
                }
            #pragma unroll
            for (int nt = 0; nt < 8; ++nt) {
                int col = wn*64 + nt*8 + kp2;
                float2 lg = *(const float2*)(lng + col);
                float2 lb = *(const float2*)(lnb + col);
                #pragma unroll
                for (int mt = 0; mt < 2; ++mt)
                    #pragma unroll
                    for (int hf = 0; hf < 2; ++hf) {
                        float v0 = (c[mt][nt][2*hf]   - muv[mt][hf]) * rsv[mt][hf] * lg.x + lb.x;
                        float v1 = (c[mt][nt][2*hf+1] - muv[mt][hf]) * rsv[mt][hf] * lg.y + lb.y;
                        float l0, l1;
                        uint32_t hp = packbf(v0, v1, l0, l1);
                        uint32_t lp = packlo(l0, l1);
                        int rl = wm*32 + mt*16 + hf*8 + r4;
                        uint32_t xo = sb + (uint32_t)(col >> 5)*16384u
                                    + SW64((uint32_t)(rl*64 + (col & 31)*2));
                        asm volatile("st.shared.b32 [%0], %1;" :: "r"(xo), "r"(hp) : "memory");
                        asm volatile("st.shared.b32 [%0], %1;" :: "r"(xo + 8192u), "r"(lp) : "memory");
                    }
            }
        } else {
            #pragma unroll
            for (int nt = 0; nt < 8; ++nt) {
                int col = wn*64 + nt*8 + kp2;
                float2 bv = *(const float2*)(in_b + col);
                #pragma unroll
                for (int mt = 0; mt < 2; ++mt)
                    #pragma unroll
                    for (int hf = 0; hf < 2; ++hf) {
                        int pt = m_block + wm*32 + mt*16 + hf*8 + r4;
                        float v0 = (c[mt][nt][2*hf]   + bv.x) * scale;
                        float v1 = (c[mt][nt][2*hf+1] + bv.y) * scale;
                        *(float2*)(g_Q + (size_t)pt*256 + col) = make_float2(v0, v1);
                    }
            }
        }
    }
}

// ======== fused MFN kernel: L0..L4 + fragment-direct fin + irfft ========
#define FX_BYTES 131072u
#define FSLAB 49152u
#define FUSED_SMEM (131072 + 2*49152)

__global__ void __launch_bounds__(512, 1)
mfn_fused(const float* __restrict__ net1_b,
          const float* __restrict__ gW, const float* __restrict__ gb,
          const float* __restrict__ gmu, const float* __restrict__ gga,
          const float* __restrict__ coords,
          const float* __restrict__ fin_W, const float* __restrict__ fin_b,
          float* __restrict__ out) {
    extern __shared__ char smraw[];
    uint32_t sb = smem_u32(smraw);
    uint32_t stoff = sb + FX_BYTES;
    int tid = threadIdx.x, lane = tid & 31, w = tid >> 5;
    int wn = w & 3, wm = w >> 2;
    int m_block = blockIdx.x * 128;

    int sub = lane & 7, blk = lane >> 3;
    int rowoff = sub + ((blk & 1) << 3);
    uint32_t koffB = (uint32_t)((blk >> 1) << 4);
    uint32_t aoff[2][2], boff[4][2];
    #pragma unroll
    for (int mt = 0; mt < 2; ++mt)
        #pragma unroll
        for (int kh = 0; kh < 2; ++kh)
            aoff[mt][kh] = SW64((uint32_t)((wm*32 + mt*16 + rowoff)*64 + kh*32) + koffB);
    #pragma unroll
    for (int ng = 0; ng < 4; ++ng)
        #pragma unroll
        for (int kh = 0; kh < 2; ++kh)
            boff[ng][kh] = SW64((uint32_t)((wn*64 + ng*16 + rowoff)*64 + kh*32) + koffB);

    int r4 = lane >> 2, kp2 = (lane & 3)*2;
    float cx[2][2], cy[2][2], rr2[2][2];
    #pragma unroll
    for (int mt = 0; mt < 2; ++mt)
        #pragma unroll
        for (int hf = 0; hf < 2; ++hf) {
            int pt = m_block + wm*32 + mt*16 + hf*8 + r4;
            float2 xy = *(const float2*)(coords + 2*pt);
            cx[mt][hf] = xy.x; cy[mt][hf] = xy.y; rr2[mt][hf] = xy.x*xy.x + xy.y*xy.y;
        }

    auto prefetch = [&](int L, int i, uint32_t stb) {
        bool loadA; int ch, matB;
        if (L == 0)      { loadA = true;  ch = i;     matB = 3; }
        else if (i < 8)  { loadA = false; ch = i;     matB = 8 + (L-1); }
        else             { loadA = true;  ch = i - 8; matB = 3 + L; }
        const __nv_bfloat16* BHp = g_Bh + (size_t)matB*65536;
        const __nv_bfloat16* BLp = g_Bl + (size_t)matB*65536;
        int r = tid >> 2, seg = tid & 3;
        size_t go = (size_t)ch*32 + seg*8;
        if (loadA) {
            size_t aofs = (size_t)(m_block + r)*256 + go;
            uint32_t sA = stb + SW64((uint32_t)(r*64 + seg*16));
            CP16(sA, g_Z2h + aofs);
            CP16(sA + OFF_AL, g_Z2l + aofs);
        }
        #pragma unroll
        for (int it = 0; it < 2; ++it) {
            int row = r + it*128;
            uint32_t sB = stb + OFF_BH + SW64((uint32_t)(row*64 + seg*16));
            CP16(sB, BHp + (size_t)row*256 + go);
            CP16(sB + 16384u, BLp + (size_t)row*256 + go);
        }
    };

    float c[2][8][4];
    int s = 0;
    prefetch(0, 0, stoff);
    CP_COMMIT();

    for (int L = 0; L <= 4; ++L) {
        int np = (L == 0) ? 8 : 16;
        #pragma unroll
        for (int mt = 0; mt < 2; ++mt)
            #pragma unroll
            for (int nt = 0; nt < 8; ++nt)
                #pragma unroll
                for (int i = 0; i < 4; ++i) c[mt][nt][i] = 0.f;

        for (int i = 0; i < np; ++i) {
            CP_WAIT0();
            __syncthreads();
            {
                int nL = L, ni = i + 1;
                if (ni == np) { nL = L + 1; ni = 0; }
                if (nL <= 4) {
                    prefetch(nL, ni, stoff + (uint32_t)((s+1) & 1)*FSLAB);
                    CP_COMMIT();
                }
            }
            bool isx = (L > 0 && i < 8);
            uint32_t stb = stoff + (uint32_t)(s & 1)*FSLAB;
            uint32_t Abase = isx ? (sb + (uint32_t)i*16384u) : stb;
            uint32_t Bbase = stb;
            #pragma unroll
            for (int kh = 0; kh < 2; ++kh) {
                uint32_t ah[2][4], al[2][4];
                ldsm4(ah[0], Abase + aoff[0][kh]);
                ldsm4(ah[1], Abase + aoff[1][kh]);
                ldsm4(al[0], Abase + OFF_AL + aoff[0][kh]);
                ldsm4(al[1], Abase + OFF_AL + aoff[1][kh]);
                #pragma unroll
                for (int ng = 0; ng < 4; ++ng) {
                    uint32_t bh[4], bl[4];
                    ldsm4(bh, Bbase + OFF_BH + boff[ng][kh]);
                    ldsm4(bl, Bbase + OFF_BL + boff[ng][kh]);
                    #pragma unroll
                    for (int mt = 0; mt < 2; ++mt) {
                        mma16816(c[mt][2*ng],   ah[mt], bh[0], bh[2]);
                        mma16816(c[mt][2*ng+1], ah[mt], bh[1], bh[3]);
                        mma16816(c[mt][2*ng],   al[mt], bh[0], bh[2]);
                        mma16816(c[mt][2*ng+1], al[mt], bh[1], bh[3]);
                        mma16816(c[mt][2*ng],   ah[mt], bl[0], bl[2]);
                        mma16816(c[mt][2*ng+1], ah[mt], bl[1], bl[3]);
                    }
                }
            }
            ++s;
        }
        __syncthreads();

        #pragma unroll
        for (int nt = 0; nt < 8; ++nt) {
            int col = wn*64 + nt*8 + kp2;
            if (L > 0) {
                float2 bv = *(const float2*)(net1_b + (L-1)*256 + col);
                #pragma unroll
                for (int mt = 0; mt < 2; ++mt) {
                    c[mt][nt][0] += bv.x; c[mt][nt][1] += bv.y;
                    c[mt][nt][2] += bv.x; c[mt][nt][3] += bv.y;
                }
            }
            int idx = L*256 + col;
            float4 wv = *(const float4*)(gW + 2*idx);
            float4 mv = *(const float4*)(gmu + 2*idx);
            float2 bb = *(const float2*)(gb + idx);
            float2 gv = *(const float2*)(gga + idx);
            float mu20 = mv.x*mv.x + mv.y*mv.y;
            float mu21 = mv.z*mv.z + mv.w*mv.w;
            #pragma unroll
            for (int mt = 0; mt < 2; ++mt)
                #pragma unroll
                for (int hf = 0; hf < 2; ++hf) {
                    float x = cx[mt][hf], y = cy[mt][hf], r2 = rr2[mt][hf];
                    float D0 = r2 + mu20 - 2.f*(x*mv.x + y*mv.y);
                    float D1 = r2 + mu21 - 2.f*(x*mv.z + y*mv.w);
                    float v0 = c[mt][nt][2*hf]   * (sinf(wv.x*x + wv.y*y + bb.x) * __expf(-0.5f*D0*gv.x));
                    float v1 = c[mt][nt][2*hf+1] * (sinf(wv.z*x + wv.w*y + bb.y) * __expf(-0.5f*D1*gv.y));
                    if (L < 4) {
                        float l0, l1;
                        uint32_t hp = packbf(v0, v1, l0, l1);
                        uint32_t lp = packlo(l0, l1);
                        int rl = wm*32 + mt*16 + hf*8 + r4;
                        uint32_t xo = sb + (uint32_t)(col >> 5)*16384u
                                    + SW64((uint32_t)(rl*64 + (col & 31)*2));
                        asm volatile("st.shared.b32 [%0], %1;" :: "r"(xo), "r"(hp) : "memory");
                        asm volatile("st.shared.b32 [%0], %1;" :: "r"(xo + OFF_AL), "r"(lp) : "memory");
                    } else {
                        c[mt][nt][2*hf]   = v0;
                        c[mt][nt][2*hf+1] = v1;
                    }
                }
        }
    }
    __syncthreads();

    {
        float* sW   = (float*)smraw;
        float* sF   = sW + 128*36*4;
        float* sTab = sF + 128*36;
        if (tid < 16) {
            float sv, cv;
            sincosf(0.39269908169872414f * (float)tid, &sv, &cv);
            sTab[2*tid] = cv; sTab[2*tid+1] = sv;
        }
        for (int g = 0; g < 36; ++g) {
            ull acc0 = 0ull, acc1 = 0ull, acc2 = 0ull, acc3 = 0ull;
            const float* Wg = fin_W + g*256 + wn*64 + kp2;
            #pragma unroll
            for (int nt = 0; nt < 8; ++nt) {
                float2 wvv = *(const float2*)(Wg + nt*8);
                ull wp = pack2(wvv.x, wvv.y);
                fma2(acc0, pack2(c[0][nt][0], c[0][nt][1]), wp);
                fma2(acc1, pack2(c[0][nt][2], c[0][nt][3]), wp);
                fma2(acc2, pack2(c[1][nt][0], c[1][nt][1]), wp);
                fma2(acc3, pack2(c[1][nt][2], c[1][nt][3]), wp);
            }
            float f0 = fold2(acc0), f1 = fold2(acc1), f2 = fold2(acc2), f3 = fold2(acc3);
            f0 += __shfl_xor_sync(0xffffffffu, f0, 1); f0 += __shfl_xor_sync(0xffffffffu, f0, 2);
            f1 += __shfl_xor_sync(0xffffffffu, f1, 1); f1 += __shfl_xor_sync(0xffffffffu, f1, 2);
            f2 += __shfl_xor_sync(0xffffffffu, f2, 1); f2 += __shfl_xor_sync(0xffffffffu, f2, 2);
            f3 += __shfl_xor_sync(0xffffffffu, f3, 1); f3 += __shfl_xor_sync(0xffffffffu, f3, 2);
            if ((lane & 3) == 0) {
                int rbase = wm*32 + r4;
                sW[(rbase     )*144 + g*4 + wn] = f0;
                sW[(rbase +  8)*144 + g*4 + wn] = f1;
                sW[(rbase + 16)*144 + g*4 + wn] = f2;
                sW[(rbase + 24)*144 + g*4 + wn] = f3;
            }
        }
        __syncthreads();
        if (tid < 128) {
            const float* wp = sW + tid*144;
            #pragma unroll 4
            for (int g = 0; g < 36; ++g)
                sF[tid*36 + g] = wp[g*4] + wp[g*4+1] + wp[g*4+2] + wp[g*4+3] + fin_b[g];
        }
        __syncthreads();
        int pc = tid & 255;
        int pp2 = pc >> 1, ch = pc & 1;
        int tg = tid >> 8;
        const float* Fp = &sF[pp2*36];
        int b = m_block >> 14;
        int n0p = (m_block & (NPTS-1)) + pp2;
        #pragma unroll
        for (int it = 0; it < 8; ++it) {
            int tt = tg + 2*it;
            float a = Fp[ch*2];
            float f8 = Fp[8*4 + ch*2];
            a += (tt & 1) ? -f8 : f8;
            #pragma unroll
            for (int fq = 1; fq < 8; ++fq) {
                float re = Fp[fq*4 + ch*2], im = Fp[fq*4 + ch*2 + 1];
                int k = (fq*tt) & 15;
                a += 2.f * (re*sTab[2*k] - im*sTab[2*k+1]);
            }
            out[(((b*16 + tt)*NPTS) + n0p)*2 + ch] = 0.25f * a;
        }
    }
}

// ======== attention (scalar, occupancy-tuned) ========
#define ATTN_SMF (5120 + P*512)
__global__ void __launch_bounds__(256, 4) attn_kernel() {
    extern __shared__ float smf[];
    float* sA = smf;
    float* sS = sA + 5120;
    int t = threadIdx.x, lane = t & 31, w = t >> 5;
    int bid = blockIdx.x, b = bid >> 10, n0 = (bid & 1023) * P;
    size_t base = (size_t)(b*NPTS + n0) * 256;
    #pragma unroll
    for (int p = 0; p < P; ++p) sA[t*PP + p] = g_Q[base + (size_t)p*256 + t];
    __syncthreads();
    #pragma unroll
    for (int rep = 0; rep < 2; ++rep) {
        int pair = t + rep*256, hh = pair >> 6, m = pair & 63;
        const float* Kp = &g_Kt[((b*8 + hh)*32)*M_KV + m];
        ull a2[8];
        #pragma unroll
        for (int j = 0; j < 8; ++j) a2[j] = 0ull;
        #pragma unroll 4
        for (int k = 0; k < 32; ++k) {
            float kv = Kp[k*M_KV];
            ull kk = pack2(kv, kv);
            const ulonglong2* col = (const ulonglong2*)(sA + (hh*32 + k)*PP);
            #pragma unroll
            for (int q = 0; q < 4; ++q) { ulonglong2 x = col[q]; fma2(a2[2*q], x.x, kk); fma2(a2[2*q+1], x.y, kk); }
        }
        #pragma unroll
        for (int j = 0; j < 8; ++j) {
            float lo, hi; unpack2(a2[j], lo, hi);
            sS[(2*j)*512 + pair] = lo; sS[(2*j+1)*512 + pair] = hi;
        }
    }
    __syncthreads();
    for (int rr = 0; rr < 16; ++rr) {
        int r = w + rr*8, p = r >> 3, hh = r & 7;
        float* bs = &sS[p*512 + hh*64];
        float v0 = bs[lane], v1 = bs[lane+32];
        float mx = fmaxf(v0, v1);
        #pragma unroll
        for (int o = 16; o; o >>= 1) mx = fmaxf(mx, __shfl_xor_sync(0xffffffffu, mx, o));
        float e0 = __expf(v0-mx), e1 = __expf(v1-mx), sum = e0 + e1;
        #pragma unroll
        for (int o = 16; o; o >>= 1) sum += __shfl_xor_sync(0xffffffffu, sum, o);
        float inv = 1.f/sum;
        bs[lane] = e0*inv; bs[lane+32] = e1*inv;
    }
    __syncthreads();
    // ctx in two passes of 8 points (register pressure: acc[8] = 16 regs)
    {
        int hh = t >> 5;
        const float* Vb = g_Vt + b*32*512;
        #pragma unroll
        for (int half = 0; half < 2; ++half) {
            ull acc[8];
            #pragma unroll
            for (int p = 0; p < 8; ++p) acc[p] = 0ull;
            #pragma unroll 2
            for (int m = 0; m < M_KV; m += 2) {
                ull vv = *(const ull*)(Vb + ((m>>1)*256 + t)*2);
                #pragma unroll
                for (int p = 0; p < 8; ++p)
                    fma2(acc[p], *(const ull*)(&sS[(half*8 + p)*512 + hh*64 + m]), vv);
            }
            #pragma unroll
            for (int p = 0; p < 8; ++p) {
                float v = fold2(acc[p]);
                __nv_bfloat16 h = __float2bfloat16_rn(v);
                g_X0h[base + (size_t)(half*8 + p)*256 + t] = h;
                g_X0l[base + (size_t)(half*8 + p)*256 + t] = __float2bfloat16_rn(v - __bfloat162float(h));
            }
        }
    }
}

// ======== launch ========
extern "C" void kernel_launch(void* const* d_in, const int* in_sizes, int n_in,
                              void* d_out, int out_size) {
    const float* z_multi=(const float*)d_in[0];  const float* coords=(const float*)d_in[1];
    const float* gabor_W=(const float*)d_in[2];  const float* gabor_b=(const float*)d_in[3];
    const float* gabor_mu=(const float*)d_in[4]; const float* gabor_ga=(const float*)d_in[5];
    const float* net1_W=(const float*)d_in[6];   const float* net1_b=(const float*)d_in[7];
    const float* net2_W=(const float*)d_in[8];   const float* qp_W1=(const float*)d_in[9];
    const float* qp_b1=(const float*)d_in[10];   const float* qp_W2=(const float*)d_in[11];
    const float* qp_b2=(const float*)d_in[12];   const float* in_W=(const float*)d_in[13];
    const float* in_b=(const float*)d_in[14];    const float* out_W=(const float*)d_in[15];
    const float* out_b=(const float*)d_in[16];   const float* lnq_g=(const float*)d_in[17];
    const float* lnq_b=(const float*)d_in[18];   const float* lnkv_g=(const float*)d_in[19];
    const float* lnkv_b=(const float*)d_in[20];  const float* fin_W=(const float*)d_in[21];
    const float* fin_b=(const float*)d_in[22];
    float* out = (float*)d_out;

    cudaFuncSetAttribute(gemm_bias,   cudaFuncAttributeMaxDynamicSharedMemorySize, GEMM_SMEM);
    cudaFuncSetAttribute(qproj_fused, cudaFuncAttributeMaxDynamicSharedMemorySize, QP_SMEM);
    cudaFuncSetAttribute(mfn_fused,   cudaFuncAttributeMaxDynamicSharedMemorySize, FUSED_SMEM);
    cudaFuncSetAttribute(attn_kernel, cudaFuncAttributeMaxDynamicSharedMemorySize, ATTN_SMF*4);

    conv_w<<<dim3(256,14), 256>>>(qp_W2, in_W, out_W, net2_W, net1_W);
    kv_kernel<<<BATCH*M_KV/8, 256>>>(z_multi, lnkv_g, lnkv_b, in_b);

    int G = TOTM/128;
    const float qscale = 0.17677669529663687f;  // 1/sqrt(32)
    qproj_fused<<<G,512,QP_SMEM>>>(qp_W1, qp_b1, qp_b2, lnq_g, lnq_b, in_b, qscale, coords);
    attn_kernel<<<BATCH*(NPTS/P), 256, ATTN_SMF*4>>>();
    gemm_bias<<<G,512,GEMM_SMEM>>>(0, 2, 1, out_b);
    mfn_fused<<<G,512,FUSED_SMEM>>>(net1_b, gabor_W, gabor_b, gabor_mu, gabor_ga, coords,
                                    fin_W, fin_b, out);
}